// round 13
// baseline (speedup 1.0000x reference)
#include <cuda_runtime.h>
#include <cuda_bf16.h>
#include <cstdint>

#define NB 1024
#define LD 32
#define HD 64
#define NT 256
#define SELF_SCALE 0.5f
#define INT_SCALE 0.3f

// ---------------- device scratch ----------------
__device__ __align__(16) float g_A[NB * HD];     // a_i   [i][k]
__device__ __align__(16) float g_Bv[NB * HD];    // b_j   [j][k]
__device__ __align__(16) float g_CI[NB * LD];
__device__ __align__(16) float g_CJ[NB * LD];
__device__ __align__(16) float g_SELF[NB * LD];
__device__ __align__(16) float g_Hh[NB * LD];
__device__ __align__(16) float g_CS[NB * LD];    // cos(ph_j * pw_l)
__device__ __align__(16) float g_SN[NB * LD];    // sin(ph_j * pw_l)
__device__ __align__(16) float g_S[NB * NB];     // s_ij (4 MB)
__device__ __align__(16) float g_Q[NB * LD];     // quantum sum per (i,l)
__device__ float g_SS[NB];                       // sum_j s_ij
__device__ float g_AG[NB];

__device__ __forceinline__ float tanh_fast(float x) {
    float e = __expf(2.0f * x);
    return 1.0f - __fdividef(2.0f, e + 1.0f);
}

__device__ __forceinline__ uint32_t smem_u32(const void* p) {
    uint32_t a;
    asm("{ .reg .u64 t; cvta.to.shared.u64 t, %1; cvt.u32.u64 %0, t; }" : "=r"(a) : "l"(p));
    return a;
}

#define LDM4(r0, r1, r2, r3, addr)                                          \
    asm volatile("ldmatrix.sync.aligned.m8n8.x4.shared.b16 {%0,%1,%2,%3}, [%4];" \
        : "=r"(r0), "=r"(r1), "=r"(r2), "=r"(r3) : "r"(addr))

#define MMA_BF16(c, a0, a1, a2, a3, b0, b1)                                 \
    asm volatile("mma.sync.aligned.m16n8k16.row.col.f32.bf16.bf16.f32 "     \
        "{%0,%1,%2,%3}, {%4,%5,%6,%7}, {%8,%9}, {%0,%1,%2,%3};"             \
        : "+f"((c)[0]), "+f"((c)[1]), "+f"((c)[2]), "+f"((c)[3])            \
        : "r"(a0), "r"(a1), "r"(a2), "r"(a3), "r"(b0), "r"(b1))

// phase2 SMEM layout (dynamic, byte offsets)
#define OFF_SW_HI 0        // Wi2 hi  [r][k] 64x128B  (8 KB)
#define OFF_SW_LO 8192     // Wi2 lo                  (8 KB)
#define OFF_SX_HI 16384    // x1 hi   [j][k] 128x128B (16 KB)
#define OFF_SX_LO 32768    // x1 lo                   (16 KB)
#define OFF_SS    49152    // s_j (128 floats)
#define OFF_WRED  49664    // colacc partials [2][64]
#define SMEM_TOT  50176

__device__ __forceinline__ uint32_t sw128(uint32_t off) {
    return off ^ ((off >> 3) & 0x70);
}

// ---------------------------------------------------------------------------
// Phase 1 v2: 64 blocks x 256 thr, 16 nodes/block, weights staged in SMEM
// (transposed so compute-side SMEM reads are lane-consecutive).
// ---------------------------------------------------------------------------
// float offsets into dynamic smem
#define P1_S1T   0               // [32][64]   2048
#define P1_S2T   2048            // [64][64]   4096
#define P1_S3T   6144            // [64][32]   2048
#define P1_WI1T  8192            // [128][64]  8192
#define P1_WCT   16384           // [64][32]   2048
#define P1_BS1   18432           // 64
#define P1_BS2   18496           // 64
#define P1_BS3   18560           // 32
#define P1_BI1   18592           // 64
#define P1_H     18656           // [16][32]   512
#define P1_T1    19168           // [16][64]   1024
#define P1_T2    20192           // [16][64]   1024
#define P1_DH    21216           // [16][32]   512
#define P1_PH    21728           // 16
#define P1_TOT_F 21744
#define P1_SMEM  (P1_TOT_F * 4)

__global__ void __launch_bounds__(NT) phase1_kernel(
    const float* __restrict__ state,
    const float* __restrict__ Ws1, const float* __restrict__ bs1,
    const float* __restrict__ Ws2, const float* __restrict__ bs2,
    const float* __restrict__ Ws3, const float* __restrict__ bs3,
    const float* __restrict__ Wi1, const float* __restrict__ bi1,
    const float* __restrict__ Wc,  const float* __restrict__ aggr,
    const float* __restrict__ phase_w)
{
    extern __shared__ float sm[];
    const int tid = threadIdx.x;
    const int i0 = blockIdx.x * 16;

    // ---- coalesced weight loads, transposed stores ----
    for (int idx = tid; idx < 64 * 32; idx += NT) {          // Ws1 [u][l]
        int u = idx >> 5, l = idx & 31;
        sm[P1_S1T + l * 64 + u] = Ws1[idx];
    }
    for (int idx = tid; idx < 64 * 64; idx += NT) {          // Ws2 [u][k]
        int u = idx >> 6, k = idx & 63;
        sm[P1_S2T + k * 64 + u] = Ws2[idx];
    }
    for (int idx = tid; idx < 32 * 64; idx += NT) {          // Ws3 [l][k]
        int l = idx >> 6, k = idx & 63;
        sm[P1_S3T + k * 32 + l] = Ws3[idx];
    }
    for (int idx = tid; idx < 64 * 128; idx += NT) {         // Wi1 [u][c]
        int u = idx >> 7, c = idx & 127;
        sm[P1_WI1T + c * 64 + u] = Wi1[idx];
    }
    for (int idx = tid; idx < 32 * 64; idx += NT) {          // Wc [l][m]
        int l = idx >> 6, m = idx & 63;
        sm[P1_WCT + m * 32 + l] = Wc[idx];
    }
    if (tid < 64) sm[P1_BS1 + tid] = bs1[tid];
    if (tid >= 64 && tid < 128) sm[P1_BS2 + tid - 64] = bs2[tid - 64];
    if (tid >= 128 && tid < 160) sm[P1_BS3 + tid - 128] = bs3[tid - 128];
    if (tid >= 160 && tid < 224) sm[P1_BI1 + tid - 160] = bi1[tid - 160];

    // state: 16 nodes x 33
    for (int idx = tid; idx < 16 * 33; idx += NT) {
        int n = idx / 33, c = idx % 33;
        float v = state[(i0 + n) * 33 + idx % 33];
        if (c < 32) sm[P1_H + n * 32 + c] = v;
        else        sm[P1_PH + n] = v;
    }
    __syncthreads();

    const int u = tid & 63;
    const int nq = tid >> 6;     // 0..3
    const int l5 = tid & 31;
    const int n5 = tid >> 5;     // 0..7

    // ---- layer 1 ----
#pragma unroll
    for (int g = 0; g < 4; g++) {
        int n = g * 4 + nq;
        float acc = sm[P1_BS1 + u];
#pragma unroll
        for (int l = 0; l < 32; l++)
            acc += sm[P1_S1T + l * 64 + u] * sm[P1_H + n * 32 + l];
        sm[P1_T1 + n * 64 + u] = tanhf(acc);
    }
    __syncthreads();

    // ---- layer 2 ----
#pragma unroll
    for (int g = 0; g < 4; g++) {
        int n = g * 4 + nq;
        float acc = sm[P1_BS2 + u];
#pragma unroll
        for (int k = 0; k < 64; k++)
            acc += sm[P1_S2T + k * 64 + u] * sm[P1_T1 + n * 64 + k];
        sm[P1_T2 + n * 64 + u] = tanhf(acc);
    }
    __syncthreads();

    // ---- layer 3 (self term) ----
#pragma unroll
    for (int g = 0; g < 2; g++) {
        int n = g * 8 + n5;
        float acc = sm[P1_BS3 + l5];
#pragma unroll
        for (int k = 0; k < 64; k++)
            acc += sm[P1_S3T + k * 32 + l5] * sm[P1_T2 + n * 64 + k];
        sm[P1_DH + n * 32 + l5] = acc;
        g_SELF[(i0 + n) * 32 + l5] = acc;
        g_Hh[(i0 + n) * 32 + l5] = sm[P1_H + n * 32 + l5];
    }
    __syncthreads();

    // ---- a_i, b_i ----
#pragma unroll
    for (int g = 0; g < 4; g++) {
        int n = g * 4 + nq;
        float a = 0.0f, b = sm[P1_BI1 + u];
#pragma unroll
        for (int l = 0; l < 32; l++) {
            float hv = sm[P1_H + n * 32 + l];
            float dv = sm[P1_DH + n * 32 + l];
            a += sm[P1_WI1T + l * 64 + u] * hv + sm[P1_WI1T + (64 + l) * 64 + u] * dv;
            b += sm[P1_WI1T + (32 + l) * 64 + u] * hv + sm[P1_WI1T + (96 + l) * 64 + u] * dv;
        }
        g_A[(i0 + n) * 64 + u] = a;
        g_Bv[(i0 + n) * 64 + u] = b;
    }

    // ---- ci/cj + cos/sin tables ----
#pragma unroll
    for (int g = 0; g < 2; g++) {
        int n = g * 8 + n5;
        float ci = 0.0f, cj = 0.0f;
#pragma unroll
        for (int m = 0; m < 32; m++) {
            float hv = sm[P1_H + n * 32 + m];
            ci += sm[P1_WCT + m * 32 + l5] * hv;
            cj += sm[P1_WCT + (32 + m) * 32 + l5] * hv;
        }
        g_CI[(i0 + n) * 32 + l5] = ci;
        g_CJ[(i0 + n) * 32 + l5] = cj;
        float cs, sn;
        sincosf(sm[P1_PH + n] * phase_w[l5], &sn, &cs);
        g_CS[(i0 + n) * 32 + l5] = cs;
        g_SN[(i0 + n) * 32 + l5] = sn;
    }
    if (tid < 16)
        g_AG[i0 + tid] = 1.0f / (1.0f + expf(-aggr[i0 + tid]));
}

// ---------------------------------------------------------------------------
// Phase 1.5 v2: 128 blocks x 8 warps; warp owns one i, streams all j.
// 4-way j unroll for independent shfl chains; x8 L1 reuse of j-stream.
// ---------------------------------------------------------------------------
__global__ void __launch_bounds__(NT) p15_kernel(const float* __restrict__ bc)
{
    const int tid = threadIdx.x;
    const int lane = tid & 31;
    const int warp = tid >> 5;
    const int i = blockIdx.x * 8 + warp;

    const float agg_i = g_AG[i];
    const float hi_l  = g_Hh[i * LD + lane];
    const float zi    = g_CI[i * LD + lane] + bc[lane];
    const float cs_i  = g_CS[i * LD + lane];
    const float sn_i  = g_SN[i * LD + lane];

    float qacc = 0.0f, ssum = 0.0f;

#pragma unroll 1
    for (int j0 = 0; j0 < NB; j0 += 4) {
        float e[4], d2[4];
#pragma unroll
        for (int u = 0; u < 4; u++) {
            float hj = g_Hh[(j0 + u) * LD + lane];
            e[u] = hj - hi_l;
            d2[u] = e[u] * e[u];
        }
#pragma unroll
        for (int o = 16; o > 0; o >>= 1) {
#pragma unroll
            for (int u = 0; u < 4; u++)
                d2[u] += __shfl_xor_sync(0xffffffffu, d2[u], o);
        }
#pragma unroll
        for (int u = 0; u < 4; u++) {
            int j = j0 + u;
            float s = fminf(rsqrtf(d2[u]), 2.0f) * agg_i;
            if (j == i) s = 0.0f;
            float pf = cs_i * g_CS[j * LD + lane] + sn_i * g_SN[j * LD + lane];
            float z  = zi + g_CJ[j * LD + lane];
            float coh = __fdividef(1.0f, 1.0f + __expf(-z));
            qacc += pf * coh * e[u];
            ssum += s;
            if (lane == 0) g_S[i * NB + j] = s;
        }
    }

    g_Q[i * LD + lane] = qacc;
    if (lane == 0) g_SS[i] = ssum;
}

// ---------------------------------------------------------------------------
// Phase 2: HMMA split-bf16 pipeline (unchanged from round 12)
// ---------------------------------------------------------------------------
__global__ void __launch_bounds__(NT, 2) phase2_kernel(
    const float* __restrict__ Wi2, const float* __restrict__ bi2,
    const float* __restrict__ Wi3, const float* __restrict__ bi3,
    float* __restrict__ out)
{
    extern __shared__ char smem[];
    const uint32_t smem_base = smem_u32(smem);
    const int i = blockIdx.x;
    const int tid = threadIdx.x;
    const int lane = tid & 31;
    const int warp = tid >> 5;

    float* sSp   = (float*)(smem + OFF_SS);
    float* sWRed = (float*)(smem + OFF_WRED);

    for (int idx = tid; idx < HD * 32; idx += NT) {
        int r = idx >> 5, w = idx & 31;
        float2 v = *(const float2*)(Wi2 + r * HD + 2 * w);
        __nv_bfloat16 h0 = __float2bfloat16(v.x), h1 = __float2bfloat16(v.y);
        __nv_bfloat16 l0 = __float2bfloat16(v.x - __bfloat162float(h0));
        __nv_bfloat16 l1 = __float2bfloat16(v.y - __bfloat162float(h1));
        uint32_t hw = ((uint32_t)__bfloat16_as_ushort(h1) << 16) | __bfloat16_as_ushort(h0);
        uint32_t lw = ((uint32_t)__bfloat16_as_ushort(l1) << 16) | __bfloat16_as_ushort(l0);
        uint32_t sw = sw128(r * 128 + w * 4);
        *(uint32_t*)(smem + OFF_SW_HI + sw) = hw;
        *(uint32_t*)(smem + OFF_SW_LO + sw) = lw;
    }

    const float ak0 = g_A[i * HD + 2 * lane];
    const float ak1 = g_A[i * HD + 2 * lane + 1];

    const int jb = (warp & 1) * 64;
    const int rb = (warp >> 1) * 16;

    uint32_t rowAoff[4], swA[4];
#pragma unroll
    for (int mt = 0; mt < 4; mt++) {
        uint32_t ro = (uint32_t)(jb + mt * 16 + (lane & 15)) * 128;
        rowAoff[mt] = ro;
        swA[mt] = (ro >> 3) & 0x70;
    }
    const uint32_t kaddA = (uint32_t)(lane & 16);
    const uint32_t rowBoff = (uint32_t)(rb + (lane & 7) + ((lane & 16) >> 1)) * 128;
    const uint32_t swB = (rowBoff >> 3) & 0x70;
    const uint32_t kaddB = (uint32_t)((lane & 8) << 1);

    float bi2v[4];
#pragma unroll
    for (int nt = 0; nt < 2; nt++)
#pragma unroll
        for (int cb = 0; cb < 2; cb++)
            bi2v[nt * 2 + cb] = bi2[rb + nt * 8 + (lane & 3) * 2 + cb];

    float colacc[4] = {0.f, 0.f, 0.f, 0.f};

    for (int t = 0; t < 8; t++) {
        const int j0 = t * 128;

#pragma unroll 2
        for (int v = 0; v < 16; v++) {
            int jl = warp * 16 + v;
            float2 b2 = *(const float2*)(g_Bv + (j0 + jl) * HD + 2 * lane);
            float x0 = tanh_fast(ak0 + b2.x);
            float x1v = tanh_fast(ak1 + b2.y);
            __nv_bfloat16 h0 = __float2bfloat16(x0), h1 = __float2bfloat16(x1v);
            __nv_bfloat16 l0 = __float2bfloat16(x0 - __bfloat162float(h0));
            __nv_bfloat16 l1 = __float2bfloat16(x1v - __bfloat162float(h1));
            uint32_t hw = ((uint32_t)__bfloat16_as_ushort(h1) << 16) | __bfloat16_as_ushort(h0);
            uint32_t lw = ((uint32_t)__bfloat16_as_ushort(l1) << 16) | __bfloat16_as_ushort(l0);
            uint32_t sw = sw128((uint32_t)jl * 128 + lane * 4);
            *(uint32_t*)(smem + OFF_SX_HI + sw) = hw;
            *(uint32_t*)(smem + OFF_SX_LO + sw) = lw;
        }
        if (tid < 128) sSp[tid] = g_S[i * NB + j0 + tid];
        __syncthreads();

        float acc[4][2][4];
#pragma unroll
        for (int mt = 0; mt < 4; mt++)
#pragma unroll
            for (int nt = 0; nt < 2; nt++)
#pragma unroll
                for (int c = 0; c < 4; c++) acc[mt][nt][c] = 0.0f;

#pragma unroll
        for (int pass = 0; pass < 3; pass++) {
            const uint32_t aB = smem_base + (pass == 1 ? OFF_SX_LO : OFF_SX_HI);
            const uint32_t bB = smem_base + (pass == 2 ? OFF_SW_LO : OFF_SW_HI);
#pragma unroll
            for (int ks = 0; ks < 4; ks++) {
                const uint32_t kb = ks * 32;
                uint32_t b0, b1, b2r, b3;
                LDM4(b0, b1, b2r, b3, bB + rowBoff + ((kb + kaddB) ^ swB));
#pragma unroll
                for (int mt = 0; mt < 4; mt++) {
                    uint32_t a0, a1, a2, a3;
                    LDM4(a0, a1, a2, a3, aB + rowAoff[mt] + ((kb + kaddA) ^ swA[mt]));
                    MMA_BF16(acc[mt][0], a0, a1, a2, a3, b0, b1);
                    MMA_BF16(acc[mt][1], a0, a1, a2, a3, b2r, b3);
                }
            }
        }

#pragma unroll
        for (int mt = 0; mt < 4; mt++) {
            float s_a = sSp[jb + mt * 16 + (lane >> 2)];
            float s_b = sSp[jb + mt * 16 + 8 + (lane >> 2)];
#pragma unroll
            for (int nt = 0; nt < 2; nt++) {
#pragma unroll
                for (int c = 0; c < 4; c++) {
                    float x2 = tanh_fast(acc[mt][nt][c] + bi2v[nt * 2 + (c & 1)]);
                    colacc[nt * 2 + (c & 1)] += (c < 2 ? s_a : s_b) * x2;
                }
            }
        }
        __syncthreads();
    }

#pragma unroll
    for (int q = 0; q < 4; q++) {
        float v = colacc[q];
        v += __shfl_xor_sync(0xffffffffu, v, 4);
        v += __shfl_xor_sync(0xffffffffu, v, 8);
        v += __shfl_xor_sync(0xffffffffu, v, 16);
        colacc[q] = v;
    }
    if (lane < 4) {
#pragma unroll
        for (int nt = 0; nt < 2; nt++)
#pragma unroll
            for (int cb = 0; cb < 2; cb++)
                sWRed[(warp & 1) * 64 + rb + nt * 8 + lane * 2 + cb] = colacc[nt * 2 + cb];
    }
    __syncthreads();

    if (tid < LD) {
        float q = g_Q[i * LD + tid];
        float sst = g_SS[i];
        float kv = sst * bi3[tid];
#pragma unroll
        for (int r = 0; r < HD; r++)
            kv += (sWRed[r] + sWRed[64 + r]) * Wi3[tid * HD + r];
        float v = kv + q;
        out[i * (LD + 1) + tid] = SELF_SCALE * g_SELF[i * LD + tid] + INT_SCALE * v;
        float av = fabsf(v);
#pragma unroll
        for (int o = 16; o > 0; o >>= 1)
            av += __shfl_down_sync(0xffffffffu, av, o);
        if (tid == 0)
            out[i * (LD + 1) + LD] = 0.1f + 0.05f * av;
    }
}

// ---------------------------------------------------------------------------
extern "C" void kernel_launch(void* const* d_in, const int* in_sizes, int n_in,
                              void* d_out, int out_size)
{
    const float* state   = (const float*)d_in[0];
    const float* Ws1     = (const float*)d_in[1];
    const float* bs1     = (const float*)d_in[2];
    const float* Ws2     = (const float*)d_in[3];
    const float* bs2     = (const float*)d_in[4];
    const float* Ws3     = (const float*)d_in[5];
    const float* bs3     = (const float*)d_in[6];
    const float* Wi1     = (const float*)d_in[7];
    const float* bi1     = (const float*)d_in[8];
    const float* Wi2     = (const float*)d_in[9];
    const float* bi2     = (const float*)d_in[10];
    const float* Wi3     = (const float*)d_in[11];
    const float* bi3     = (const float*)d_in[12];
    const float* phase_w = (const float*)d_in[13];
    const float* Wc      = (const float*)d_in[14];
    const float* bc      = (const float*)d_in[15];
    const float* aggr    = (const float*)d_in[16];
    float* out = (float*)d_out;

    cudaFuncSetAttribute(phase1_kernel,
                         cudaFuncAttributeMaxDynamicSharedMemorySize, P1_SMEM);
    cudaFuncSetAttribute(phase2_kernel,
                         cudaFuncAttributeMaxDynamicSharedMemorySize, SMEM_TOT);

    phase1_kernel<<<64, NT, P1_SMEM>>>(state, Ws1, bs1, Ws2, bs2, Ws3, bs3,
                                       Wi1, bi1, Wc, aggr, phase_w);
    p15_kernel<<<128, NT>>>(bc);
    phase2_kernel<<<NB, NT, SMEM_TOT>>>(Wi2, bi2, Wi3, bi3, out);
}

// round 14
// speedup vs baseline: 2.3848x; 2.3848x over previous
#include <cuda_runtime.h>
#include <cuda_bf16.h>
#include <cstdint>

#define NB 1024
#define LD 32
#define HD 64
#define NT 256
#define SELF_SCALE 0.5f
#define INT_SCALE 0.3f

// ---------------- device scratch ----------------
__device__ __align__(16) float g_A[NB * HD];     // a_i   [i][k]
__device__ __align__(16) float g_Bv[NB * HD];    // b_j   [j][k]
__device__ __align__(16) float g_CI[NB * LD];
__device__ __align__(16) float g_CJ[NB * LD];
__device__ __align__(16) float g_SELF[NB * LD];
__device__ __align__(16) float g_Hh[NB * LD];
__device__ __align__(16) float g_CS[NB * LD];    // cos(ph_j * pw_l)
__device__ __align__(16) float g_SN[NB * LD];    // sin(ph_j * pw_l)
__device__ __align__(16) float g_S[NB * NB];     // s_ij (4 MB)
__device__ __align__(16) float g_Q[NB * LD];     // quantum sum per (i,l)
__device__ float g_SS[NB];                       // sum_j s_ij
__device__ float g_AG[NB];

__device__ __forceinline__ float tanh_fast(float x) {
    float e = __expf(2.0f * x);
    return 1.0f - __fdividef(2.0f, e + 1.0f);
}

__device__ __forceinline__ uint32_t smem_u32(const void* p) {
    uint32_t a;
    asm("{ .reg .u64 t; cvta.to.shared.u64 t, %1; cvt.u32.u64 %0, t; }" : "=r"(a) : "l"(p));
    return a;
}

#define LDM4(r0, r1, r2, r3, addr)                                          \
    asm volatile("ldmatrix.sync.aligned.m8n8.x4.shared.b16 {%0,%1,%2,%3}, [%4];" \
        : "=r"(r0), "=r"(r1), "=r"(r2), "=r"(r3) : "r"(addr))

#define MMA_BF16(c, a0, a1, a2, a3, b0, b1)                                 \
    asm volatile("mma.sync.aligned.m16n8k16.row.col.f32.bf16.bf16.f32 "     \
        "{%0,%1,%2,%3}, {%4,%5,%6,%7}, {%8,%9}, {%0,%1,%2,%3};"             \
        : "+f"((c)[0]), "+f"((c)[1]), "+f"((c)[2]), "+f"((c)[3])            \
        : "r"(a0), "r"(a1), "r"(a2), "r"(a3), "r"(b0), "r"(b1))

// phase2 SMEM layout (dynamic, byte offsets)
#define OFF_SW_HI 0        // Wi2 hi  [r][k] 64x128B  (8 KB)
#define OFF_SW_LO 8192     // Wi2 lo                  (8 KB)
#define OFF_SX_HI 16384    // x1 hi   [j][k] 128x128B (16 KB)
#define OFF_SX_LO 32768    // x1 lo                   (16 KB)
#define OFF_SS    49152    // s_j (128 floats)
#define OFF_WRED  49664    // colacc partials [2][64]
#define SMEM_TOT  50176

__device__ __forceinline__ uint32_t sw128(uint32_t off) {
    return off ^ ((off >> 3) & 0x70);
}

// ---------------------------------------------------------------------------
// Phase 1 v2: 64 blocks x 256 thr, 16 nodes/block, weights staged in SMEM
// ---------------------------------------------------------------------------
#define P1_S1T   0               // [32][64]   2048
#define P1_S2T   2048            // [64][64]   4096
#define P1_S3T   6144            // [64][32]   2048
#define P1_WI1T  8192            // [128][64]  8192
#define P1_WCT   16384           // [64][32]   2048
#define P1_BS1   18432           // 64
#define P1_BS2   18496           // 64
#define P1_BS3   18560           // 32
#define P1_BI1   18592           // 64
#define P1_H     18656           // [16][32]   512
#define P1_T1    19168           // [16][64]   1024
#define P1_T2    20192           // [16][64]   1024
#define P1_DH    21216           // [16][32]   512
#define P1_PH    21728           // 16
#define P1_TOT_F 21744
#define P1_SMEM  (P1_TOT_F * 4)

__global__ void __launch_bounds__(NT) phase1_kernel(
    const float* __restrict__ state,
    const float* __restrict__ Ws1, const float* __restrict__ bs1,
    const float* __restrict__ Ws2, const float* __restrict__ bs2,
    const float* __restrict__ Ws3, const float* __restrict__ bs3,
    const float* __restrict__ Wi1, const float* __restrict__ bi1,
    const float* __restrict__ Wc,  const float* __restrict__ aggr,
    const float* __restrict__ phase_w)
{
    extern __shared__ float sm[];
    const int tid = threadIdx.x;
    const int i0 = blockIdx.x * 16;

    for (int idx = tid; idx < 64 * 32; idx += NT) {          // Ws1 [u][l]
        int u = idx >> 5, l = idx & 31;
        sm[P1_S1T + l * 64 + u] = Ws1[idx];
    }
    for (int idx = tid; idx < 64 * 64; idx += NT) {          // Ws2 [u][k]
        int u = idx >> 6, k = idx & 63;
        sm[P1_S2T + k * 64 + u] = Ws2[idx];
    }
    for (int idx = tid; idx < 32 * 64; idx += NT) {          // Ws3 [l][k]
        int l = idx >> 6, k = idx & 63;
        sm[P1_S3T + k * 32 + l] = Ws3[idx];
    }
    for (int idx = tid; idx < 64 * 128; idx += NT) {         // Wi1 [u][c]
        int u = idx >> 7, c = idx & 127;
        sm[P1_WI1T + c * 64 + u] = Wi1[idx];
    }
    for (int idx = tid; idx < 32 * 64; idx += NT) {          // Wc [l][m]
        int l = idx >> 6, m = idx & 63;
        sm[P1_WCT + m * 32 + l] = Wc[idx];
    }
    if (tid < 64) sm[P1_BS1 + tid] = bs1[tid];
    if (tid >= 64 && tid < 128) sm[P1_BS2 + tid - 64] = bs2[tid - 64];
    if (tid >= 128 && tid < 160) sm[P1_BS3 + tid - 128] = bs3[tid - 128];
    if (tid >= 160 && tid < 224) sm[P1_BI1 + tid - 160] = bi1[tid - 160];

    for (int idx = tid; idx < 16 * 33; idx += NT) {
        int n = idx / 33, c = idx % 33;
        float v = state[(i0 + n) * 33 + c];
        if (c < 32) sm[P1_H + n * 32 + c] = v;
        else        sm[P1_PH + n] = v;
    }
    __syncthreads();

    const int u = tid & 63;
    const int nq = tid >> 6;     // 0..3
    const int l5 = tid & 31;
    const int n5 = tid >> 5;     // 0..7

#pragma unroll
    for (int g = 0; g < 4; g++) {
        int n = g * 4 + nq;
        float acc = sm[P1_BS1 + u];
#pragma unroll
        for (int l = 0; l < 32; l++)
            acc += sm[P1_S1T + l * 64 + u] * sm[P1_H + n * 32 + l];
        sm[P1_T1 + n * 64 + u] = tanhf(acc);
    }
    __syncthreads();

#pragma unroll
    for (int g = 0; g < 4; g++) {
        int n = g * 4 + nq;
        float acc = sm[P1_BS2 + u];
#pragma unroll
        for (int k = 0; k < 64; k++)
            acc += sm[P1_S2T + k * 64 + u] * sm[P1_T1 + n * 64 + k];
        sm[P1_T2 + n * 64 + u] = tanhf(acc);
    }
    __syncthreads();

#pragma unroll
    for (int g = 0; g < 2; g++) {
        int n = g * 8 + n5;
        float acc = sm[P1_BS3 + l5];
#pragma unroll
        for (int k = 0; k < 64; k++)
            acc += sm[P1_S3T + k * 32 + l5] * sm[P1_T2 + n * 64 + k];
        sm[P1_DH + n * 32 + l5] = acc;
        g_SELF[(i0 + n) * 32 + l5] = acc;
        g_Hh[(i0 + n) * 32 + l5] = sm[P1_H + n * 32 + l5];
    }
    __syncthreads();

#pragma unroll
    for (int g = 0; g < 4; g++) {
        int n = g * 4 + nq;
        float a = 0.0f, b = sm[P1_BI1 + u];
#pragma unroll
        for (int l = 0; l < 32; l++) {
            float hv = sm[P1_H + n * 32 + l];
            float dv = sm[P1_DH + n * 32 + l];
            a += sm[P1_WI1T + l * 64 + u] * hv + sm[P1_WI1T + (64 + l) * 64 + u] * dv;
            b += sm[P1_WI1T + (32 + l) * 64 + u] * hv + sm[P1_WI1T + (96 + l) * 64 + u] * dv;
        }
        g_A[(i0 + n) * 64 + u] = a;
        g_Bv[(i0 + n) * 64 + u] = b;
    }

#pragma unroll
    for (int g = 0; g < 2; g++) {
        int n = g * 8 + n5;
        float ci = 0.0f, cj = 0.0f;
#pragma unroll
        for (int m = 0; m < 32; m++) {
            float hv = sm[P1_H + n * 32 + m];
            ci += sm[P1_WCT + m * 32 + l5] * hv;
            cj += sm[P1_WCT + (32 + m) * 32 + l5] * hv;
        }
        g_CI[(i0 + n) * 32 + l5] = ci;
        g_CJ[(i0 + n) * 32 + l5] = cj;
        float cs, sn;
        sincosf(sm[P1_PH + n] * phase_w[l5], &sn, &cs);
        g_CS[(i0 + n) * 32 + l5] = cs;
        g_SN[(i0 + n) * 32 + l5] = sn;
    }
    if (tid < 16)
        g_AG[i0 + tid] = 1.0f / (1.0f + expf(-aggr[i0 + tid]));
}

// ---------------------------------------------------------------------------
// Phase 1.5 v3: block per i (1024 blocks, wide parallelism restored),
// warp per 128 j, 4-way independent shfl chains, float4 s-stores.
// ---------------------------------------------------------------------------
__global__ void __launch_bounds__(NT) p15_kernel(const float* __restrict__ bc)
{
    __shared__ float sQ[8][LD];
    __shared__ float sSr[8];

    const int i = blockIdx.x;
    const int tid = threadIdx.x;
    const int lane = tid & 31;
    const int warp = tid >> 5;

    const float agg_i = g_AG[i];
    const float hi_l  = g_Hh[i * LD + lane];
    const float zi    = g_CI[i * LD + lane] + bc[lane];
    const float cs_i  = g_CS[i * LD + lane];
    const float sn_i  = g_SN[i * LD + lane];

    float qacc = 0.0f, ssum = 0.0f;

#pragma unroll 1
    for (int v0 = 0; v0 < 128; v0 += 4) {
        const int j0 = warp * 128 + v0;
        float e[4], d2[4];
#pragma unroll
        for (int u = 0; u < 4; u++) {
            float hj = g_Hh[(j0 + u) * LD + lane];
            e[u] = hj - hi_l;
            d2[u] = e[u] * e[u];
        }
#pragma unroll
        for (int o = 16; o > 0; o >>= 1) {
#pragma unroll
            for (int u = 0; u < 4; u++)
                d2[u] += __shfl_xor_sync(0xffffffffu, d2[u], o);
        }
        float sv[4];
#pragma unroll
        for (int u = 0; u < 4; u++) {
            int j = j0 + u;
            float s = fminf(rsqrtf(d2[u]), 2.0f) * agg_i;
            if (j == i) s = 0.0f;
            sv[u] = s;
            ssum += s;
            float pf = cs_i * g_CS[j * LD + lane] + sn_i * g_SN[j * LD + lane];
            float z  = zi + g_CJ[j * LD + lane];
            float coh = __fdividef(1.0f, 1.0f + __expf(-z));
            qacc += pf * coh * e[u];
        }
        if (lane == 0)
            *(float4*)(g_S + i * NB + j0) = make_float4(sv[0], sv[1], sv[2], sv[3]);
    }

    sQ[warp][lane] = qacc;
    if (lane == 0) sSr[warp] = ssum * 0.25f;  // each lane summed s 1x; ssum counted once per lane? no:
    // NOTE: ssum accumulated identically on every lane (s is lane-uniform);
    // lane 0's copy is the true per-warp sum. The 0.25f above would be wrong —
    // correct it: store the raw value.
    if (lane == 0) sSr[warp] = ssum;
    __syncthreads();

    if (tid < LD) {
        float q = 0.0f;
#pragma unroll
        for (int w = 0; w < 8; w++) q += sQ[w][tid];
        g_Q[i * LD + tid] = q;
    }
    if (tid == 0) {
        float sst = 0.0f;
#pragma unroll
        for (int w = 0; w < 8; w++) sst += sSr[w];
        g_SS[i] = sst;
    }
}

// ---------------------------------------------------------------------------
// Phase 2: HMMA split-bf16 pipeline (unchanged)
// ---------------------------------------------------------------------------
__global__ void __launch_bounds__(NT, 2) phase2_kernel(
    const float* __restrict__ Wi2, const float* __restrict__ bi2,
    const float* __restrict__ Wi3, const float* __restrict__ bi3,
    float* __restrict__ out)
{
    extern __shared__ char smem[];
    const uint32_t smem_base = smem_u32(smem);
    const int i = blockIdx.x;
    const int tid = threadIdx.x;
    const int lane = tid & 31;
    const int warp = tid >> 5;

    float* sSp   = (float*)(smem + OFF_SS);
    float* sWRed = (float*)(smem + OFF_WRED);

    for (int idx = tid; idx < HD * 32; idx += NT) {
        int r = idx >> 5, w = idx & 31;
        float2 v = *(const float2*)(Wi2 + r * HD + 2 * w);
        __nv_bfloat16 h0 = __float2bfloat16(v.x), h1 = __float2bfloat16(v.y);
        __nv_bfloat16 l0 = __float2bfloat16(v.x - __bfloat162float(h0));
        __nv_bfloat16 l1 = __float2bfloat16(v.y - __bfloat162float(h1));
        uint32_t hw = ((uint32_t)__bfloat16_as_ushort(h1) << 16) | __bfloat16_as_ushort(h0);
        uint32_t lw = ((uint32_t)__bfloat16_as_ushort(l1) << 16) | __bfloat16_as_ushort(l0);
        uint32_t sw = sw128(r * 128 + w * 4);
        *(uint32_t*)(smem + OFF_SW_HI + sw) = hw;
        *(uint32_t*)(smem + OFF_SW_LO + sw) = lw;
    }

    const float ak0 = g_A[i * HD + 2 * lane];
    const float ak1 = g_A[i * HD + 2 * lane + 1];

    const int jb = (warp & 1) * 64;
    const int rb = (warp >> 1) * 16;

    uint32_t rowAoff[4], swA[4];
#pragma unroll
    for (int mt = 0; mt < 4; mt++) {
        uint32_t ro = (uint32_t)(jb + mt * 16 + (lane & 15)) * 128;
        rowAoff[mt] = ro;
        swA[mt] = (ro >> 3) & 0x70;
    }
    const uint32_t kaddA = (uint32_t)(lane & 16);
    const uint32_t rowBoff = (uint32_t)(rb + (lane & 7) + ((lane & 16) >> 1)) * 128;
    const uint32_t swB = (rowBoff >> 3) & 0x70;
    const uint32_t kaddB = (uint32_t)((lane & 8) << 1);

    float bi2v[4];
#pragma unroll
    for (int nt = 0; nt < 2; nt++)
#pragma unroll
        for (int cb = 0; cb < 2; cb++)
            bi2v[nt * 2 + cb] = bi2[rb + nt * 8 + (lane & 3) * 2 + cb];

    float colacc[4] = {0.f, 0.f, 0.f, 0.f};

    for (int t = 0; t < 8; t++) {
        const int j0 = t * 128;

#pragma unroll 2
        for (int v = 0; v < 16; v++) {
            int jl = warp * 16 + v;
            float2 b2 = *(const float2*)(g_Bv + (j0 + jl) * HD + 2 * lane);
            float x0 = tanh_fast(ak0 + b2.x);
            float x1v = tanh_fast(ak1 + b2.y);
            __nv_bfloat16 h0 = __float2bfloat16(x0), h1 = __float2bfloat16(x1v);
            __nv_bfloat16 l0 = __float2bfloat16(x0 - __bfloat162float(h0));
            __nv_bfloat16 l1 = __float2bfloat16(x1v - __bfloat162float(h1));
            uint32_t hw = ((uint32_t)__bfloat16_as_ushort(h1) << 16) | __bfloat16_as_ushort(h0);
            uint32_t lw = ((uint32_t)__bfloat16_as_ushort(l1) << 16) | __bfloat16_as_ushort(l0);
            uint32_t sw = sw128((uint32_t)jl * 128 + lane * 4);
            *(uint32_t*)(smem + OFF_SX_HI + sw) = hw;
            *(uint32_t*)(smem + OFF_SX_LO + sw) = lw;
        }
        if (tid < 128) sSp[tid] = g_S[i * NB + j0 + tid];
        __syncthreads();

        float acc[4][2][4];
#pragma unroll
        for (int mt = 0; mt < 4; mt++)
#pragma unroll
            for (int nt = 0; nt < 2; nt++)
#pragma unroll
                for (int c = 0; c < 4; c++) acc[mt][nt][c] = 0.0f;

#pragma unroll
        for (int pass = 0; pass < 3; pass++) {
            const uint32_t aB = smem_base + (pass == 1 ? OFF_SX_LO : OFF_SX_HI);
            const uint32_t bB = smem_base + (pass == 2 ? OFF_SW_LO : OFF_SW_HI);
#pragma unroll
            for (int ks = 0; ks < 4; ks++) {
                const uint32_t kb = ks * 32;
                uint32_t b0, b1, b2r, b3;
                LDM4(b0, b1, b2r, b3, bB + rowBoff + ((kb + kaddB) ^ swB));
#pragma unroll
                for (int mt = 0; mt < 4; mt++) {
                    uint32_t a0, a1, a2, a3;
                    LDM4(a0, a1, a2, a3, aB + rowAoff[mt] + ((kb + kaddA) ^ swA[mt]));
                    MMA_BF16(acc[mt][0], a0, a1, a2, a3, b0, b1);
                    MMA_BF16(acc[mt][1], a0, a1, a2, a3, b2r, b3);
                }
            }
        }

#pragma unroll
        for (int mt = 0; mt < 4; mt++) {
            float s_a = sSp[jb + mt * 16 + (lane >> 2)];
            float s_b = sSp[jb + mt * 16 + 8 + (lane >> 2)];
#pragma unroll
            for (int nt = 0; nt < 2; nt++) {
#pragma unroll
                for (int c = 0; c < 4; c++) {
                    float x2 = tanh_fast(acc[mt][nt][c] + bi2v[nt * 2 + (c & 1)]);
                    colacc[nt * 2 + (c & 1)] += (c < 2 ? s_a : s_b) * x2;
                }
            }
        }
        __syncthreads();
    }

#pragma unroll
    for (int q = 0; q < 4; q++) {
        float v = colacc[q];
        v += __shfl_xor_sync(0xffffffffu, v, 4);
        v += __shfl_xor_sync(0xffffffffu, v, 8);
        v += __shfl_xor_sync(0xffffffffu, v, 16);
        colacc[q] = v;
    }
    if (lane < 4) {
#pragma unroll
        for (int nt = 0; nt < 2; nt++)
#pragma unroll
            for (int cb = 0; cb < 2; cb++)
                sWRed[(warp & 1) * 64 + rb + nt * 8 + lane * 2 + cb] = colacc[nt * 2 + cb];
    }
    __syncthreads();

    if (tid < LD) {
        float q = g_Q[i * LD + tid];
        float sst = g_SS[i];
        float kv = sst * bi3[tid];
#pragma unroll
        for (int r = 0; r < HD; r++)
            kv += (sWRed[r] + sWRed[64 + r]) * Wi3[tid * HD + r];
        float v = kv + q;
        out[i * (LD + 1) + tid] = SELF_SCALE * g_SELF[i * LD + tid] + INT_SCALE * v;
        float av = fabsf(v);
#pragma unroll
        for (int o = 16; o > 0; o >>= 1)
            av += __shfl_down_sync(0xffffffffu, av, o);
        if (tid == 0)
            out[i * (LD + 1) + LD] = 0.1f + 0.05f * av;
    }
}

// ---------------------------------------------------------------------------
extern "C" void kernel_launch(void* const* d_in, const int* in_sizes, int n_in,
                              void* d_out, int out_size)
{
    const float* state   = (const float*)d_in[0];
    const float* Ws1     = (const float*)d_in[1];
    const float* bs1     = (const float*)d_in[2];
    const float* Ws2     = (const float*)d_in[3];
    const float* bs2     = (const float*)d_in[4];
    const float* Ws3     = (const float*)d_in[5];
    const float* bs3     = (const float*)d_in[6];
    const float* Wi1     = (const float*)d_in[7];
    const float* bi1     = (const float*)d_in[8];
    const float* Wi2     = (const float*)d_in[9];
    const float* bi2     = (const float*)d_in[10];
    const float* Wi3     = (const float*)d_in[11];
    const float* bi3     = (const float*)d_in[12];
    const float* phase_w = (const float*)d_in[13];
    const float* Wc      = (const float*)d_in[14];
    const float* bc      = (const float*)d_in[15];
    const float* aggr    = (const float*)d_in[16];
    float* out = (float*)d_out;

    cudaFuncSetAttribute(phase1_kernel,
                         cudaFuncAttributeMaxDynamicSharedMemorySize, P1_SMEM);
    cudaFuncSetAttribute(phase2_kernel,
                         cudaFuncAttributeMaxDynamicSharedMemorySize, SMEM_TOT);

    phase1_kernel<<<64, NT, P1_SMEM>>>(state, Ws1, bs1, Ws2, bs2, Ws3, bs3,
                                       Wi1, bi1, Wc, aggr, phase_w);
    p15_kernel<<<NB, NT>>>(bc);
    phase2_kernel<<<NB, NT, SMEM_TOT>>>(Wi2, bi2, Wi3, bi3, out);
}

// round 15
// speedup vs baseline: 2.4860x; 1.0424x over previous
#include <cuda_runtime.h>
#include <cuda_bf16.h>
#include <cstdint>

#define NB 1024
#define LD 32
#define HD 64
#define NT 256
#define SELF_SCALE 0.5f
#define INT_SCALE 0.3f

// ---------------- device scratch ----------------
__device__ __align__(16) float g_A[NB * HD];     // a_i   [i][k]
__device__ __align__(16) float g_Bv[NB * HD];    // b_j   [j][k]
__device__ __align__(16) float g_CI[NB * LD];
__device__ __align__(16) float g_CJ[NB * LD];
__device__ __align__(16) float g_SELF[NB * LD];
__device__ __align__(16) float g_Hh[NB * LD];
__device__ __align__(16) float g_CS[NB * LD];    // cos(ph_j * pw_l)
__device__ __align__(16) float g_SN[NB * LD];    // sin(ph_j * pw_l)
__device__ float g_AG[NB];

__device__ __forceinline__ float tanh_fast(float x) {
    float e = __expf(2.0f * x);
    return 1.0f - __fdividef(2.0f, e + 1.0f);
}

__device__ __forceinline__ uint32_t smem_u32(const void* p) {
    uint32_t a;
    asm("{ .reg .u64 t; cvta.to.shared.u64 t, %1; cvt.u32.u64 %0, t; }" : "=r"(a) : "l"(p));
    return a;
}

#define LDM4(r0, r1, r2, r3, addr)                                          \
    asm volatile("ldmatrix.sync.aligned.m8n8.x4.shared.b16 {%0,%1,%2,%3}, [%4];" \
        : "=r"(r0), "=r"(r1), "=r"(r2), "=r"(r3) : "r"(addr))

#define MMA_BF16(c, a0, a1, a2, a3, b0, b1)                                 \
    asm volatile("mma.sync.aligned.m16n8k16.row.col.f32.bf16.bf16.f32 "     \
        "{%0,%1,%2,%3}, {%4,%5,%6,%7}, {%8,%9}, {%0,%1,%2,%3};"             \
        : "+f"((c)[0]), "+f"((c)[1]), "+f"((c)[2]), "+f"((c)[3])            \
        : "r"(a0), "r"(a1), "r"(a2), "r"(a3), "r"(b0), "r"(b1))

// phase2 SMEM layout (dynamic, byte offsets)
#define OFF_SW_HI 0        // Wi2 hi  [r][k] 64x128B  (8 KB)
#define OFF_SW_LO 8192     // Wi2 lo                  (8 KB)
#define OFF_SX_HI 16384    // x1 hi   [j][k] 128x128B (16 KB)
#define OFF_SX_LO 32768    // x1 lo                   (16 KB)
#define OFF_SS    49152    // s_j for ALL 1024 j (4 KB)
#define OFF_WRED  53248    // colacc partials [2][64] (512 B)
#define OFF_QRED  53760    // quantum partials [8][32] (1 KB)
#define OFF_SRED  54784    // ssum partials [8]
#define SMEM_TOT  55296

__device__ __forceinline__ uint32_t sw128(uint32_t off) {
    return off ^ ((off >> 3) & 0x70);
}

// ---------------------------------------------------------------------------
// Phase 1 v3: 128 blocks x 256 thr, 8 nodes/block.
// Transposed weight staging with PADDED row strides (65/33) so the
// transpose stores are bank-conflict-free (was 32-way conflicted).
// ---------------------------------------------------------------------------
#define P1_S1T   0                 // [32][65]   2080
#define P1_S2T   2080              // [64][65]   4160
#define P1_S3T   6240              // [64][33]   2112
#define P1_WI1T  8352              // [128][65]  8320
#define P1_WCT   16672             // [64][33]   2112
#define P1_BS1   18784             // 64
#define P1_BS2   18848             // 64
#define P1_BS3   18912             // 32
#define P1_BI1   18944             // 64
#define P1_H     19008             // [8][32]    256
#define P1_T1    19264             // [8][64]    512
#define P1_T2    19776             // [8][64]    512
#define P1_DH    20288             // [8][32]    256
#define P1_PH    20544             // 8
#define P1_TOT_F 20560
#define P1_SMEM  (P1_TOT_F * 4)

__global__ void __launch_bounds__(NT) phase1_kernel(
    const float* __restrict__ state,
    const float* __restrict__ Ws1, const float* __restrict__ bs1,
    const float* __restrict__ Ws2, const float* __restrict__ bs2,
    const float* __restrict__ Ws3, const float* __restrict__ bs3,
    const float* __restrict__ Wi1, const float* __restrict__ bi1,
    const float* __restrict__ Wc,  const float* __restrict__ aggr,
    const float* __restrict__ phase_w)
{
    extern __shared__ float sm[];
    const int tid = threadIdx.x;
    const int i0 = blockIdx.x * 8;

    // coalesced gmem loads; padded-stride transposed stores (conflict-free)
    for (int idx = tid; idx < 64 * 32; idx += NT) {          // Ws1 [u][l]
        int u = idx >> 5, l = idx & 31;
        sm[P1_S1T + l * 65 + u] = Ws1[idx];
    }
    for (int idx = tid; idx < 64 * 64; idx += NT) {          // Ws2 [u][k]
        int u = idx >> 6, k = idx & 63;
        sm[P1_S2T + k * 65 + u] = Ws2[idx];
    }
    for (int idx = tid; idx < 32 * 64; idx += NT) {          // Ws3 [l][k]
        int l = idx >> 6, k = idx & 63;
        sm[P1_S3T + k * 33 + l] = Ws3[idx];
    }
    for (int idx = tid; idx < 64 * 128; idx += NT) {         // Wi1 [u][c]
        int u = idx >> 7, c = idx & 127;
        sm[P1_WI1T + c * 65 + u] = Wi1[idx];
    }
    for (int idx = tid; idx < 32 * 64; idx += NT) {          // Wc [l][m]
        int l = idx >> 6, m = idx & 63;
        sm[P1_WCT + m * 33 + l] = Wc[idx];
    }
    if (tid < 64) sm[P1_BS1 + tid] = bs1[tid];
    if (tid >= 64 && tid < 128) sm[P1_BS2 + tid - 64] = bs2[tid - 64];
    if (tid >= 128 && tid < 160) sm[P1_BS3 + tid - 128] = bs3[tid - 128];
    if (tid >= 160 && tid < 224) sm[P1_BI1 + tid - 160] = bi1[tid - 160];

    for (int idx = tid; idx < 8 * 33; idx += NT) {
        int n = idx / 33, c = idx % 33;
        float v = state[(i0 + n) * 33 + c];
        if (c < 32) sm[P1_H + n * 32 + c] = v;
        else        sm[P1_PH + n] = v;
    }
    __syncthreads();

    const int u = tid & 63;
    const int nq = tid >> 6;     // 0..3
    const int l5 = tid & 31;
    const int n5 = tid >> 5;     // 0..7

#pragma unroll
    for (int g = 0; g < 2; g++) {
        int n = g * 4 + nq;
        float acc = sm[P1_BS1 + u];
#pragma unroll
        for (int l = 0; l < 32; l++)
            acc += sm[P1_S1T + l * 65 + u] * sm[P1_H + n * 32 + l];
        sm[P1_T1 + n * 64 + u] = tanhf(acc);
    }
    __syncthreads();

#pragma unroll
    for (int g = 0; g < 2; g++) {
        int n = g * 4 + nq;
        float acc = sm[P1_BS2 + u];
#pragma unroll
        for (int k = 0; k < 64; k++)
            acc += sm[P1_S2T + k * 65 + u] * sm[P1_T1 + n * 64 + k];
        sm[P1_T2 + n * 64 + u] = tanhf(acc);
    }
    __syncthreads();

    {
        int n = n5;
        float acc = sm[P1_BS3 + l5];
#pragma unroll
        for (int k = 0; k < 64; k++)
            acc += sm[P1_S3T + k * 33 + l5] * sm[P1_T2 + n * 64 + k];
        sm[P1_DH + n * 32 + l5] = acc;
        g_SELF[(i0 + n) * 32 + l5] = acc;
        g_Hh[(i0 + n) * 32 + l5] = sm[P1_H + n * 32 + l5];
    }
    __syncthreads();

#pragma unroll
    for (int g = 0; g < 2; g++) {
        int n = g * 4 + nq;
        float a = 0.0f, b = sm[P1_BI1 + u];
#pragma unroll
        for (int l = 0; l < 32; l++) {
            float hv = sm[P1_H + n * 32 + l];
            float dv = sm[P1_DH + n * 32 + l];
            a += sm[P1_WI1T + l * 65 + u] * hv + sm[P1_WI1T + (64 + l) * 65 + u] * dv;
            b += sm[P1_WI1T + (32 + l) * 65 + u] * hv + sm[P1_WI1T + (96 + l) * 65 + u] * dv;
        }
        g_A[(i0 + n) * 64 + u] = a;
        g_Bv[(i0 + n) * 64 + u] = b;
    }

    {
        int n = n5;
        float ci = 0.0f, cj = 0.0f;
#pragma unroll
        for (int m = 0; m < 32; m++) {
            float hv = sm[P1_H + n * 32 + m];
            ci += sm[P1_WCT + m * 33 + l5] * hv;
            cj += sm[P1_WCT + (32 + m) * 33 + l5] * hv;
        }
        g_CI[(i0 + n) * 32 + l5] = ci;
        g_CJ[(i0 + n) * 32 + l5] = cj;
        float cs, sn;
        sincosf(sm[P1_PH + n] * phase_w[l5], &sn, &cs);
        g_CS[(i0 + n) * 32 + l5] = cs;
        g_SN[(i0 + n) * 32 + l5] = sn;
    }
    if (tid < 8)
        g_AG[i0 + tid] = 1.0f / (1.0f + expf(-aggr[i0 + tid]));
}

// ---------------------------------------------------------------------------
// Phase 2 (fused): s/quantum prologue + HMMA split-bf16 mainloop.
// One block (256 thr) per i. Prologue: warp w handles j in [w*128, w*128+128),
// s -> SMEM (4KB), qacc/ssum in regs. Mainloop unchanged. The prologue's
// latency-bound shfl/MUFU work overlaps other blocks' tensor mainloops.
// ---------------------------------------------------------------------------
__global__ void __launch_bounds__(NT, 2) phase2_kernel(
    const float* __restrict__ Wi2, const float* __restrict__ bi2,
    const float* __restrict__ Wi3, const float* __restrict__ bi3,
    const float* __restrict__ bc,  float* __restrict__ out)
{
    extern __shared__ char smem[];
    const uint32_t smem_base = smem_u32(smem);
    const int i = blockIdx.x;
    const int tid = threadIdx.x;
    const int lane = tid & 31;
    const int warp = tid >> 5;

    float* sS    = (float*)(smem + OFF_SS);     // [1024]
    float* sWRed = (float*)(smem + OFF_WRED);
    float* sQRed = (float*)(smem + OFF_QRED);
    float* sSRed = (float*)(smem + OFF_SRED);

    // ---- stage Wi2 hi/lo into swizzled SMEM [r][k] ----
    for (int idx = tid; idx < HD * 32; idx += NT) {
        int r = idx >> 5, w = idx & 31;
        float2 v = *(const float2*)(Wi2 + r * HD + 2 * w);
        __nv_bfloat16 h0 = __float2bfloat16(v.x), h1 = __float2bfloat16(v.y);
        __nv_bfloat16 l0 = __float2bfloat16(v.x - __bfloat162float(h0));
        __nv_bfloat16 l1 = __float2bfloat16(v.y - __bfloat162float(h1));
        uint32_t hw = ((uint32_t)__bfloat16_as_ushort(h1) << 16) | __bfloat16_as_ushort(h0);
        uint32_t lw = ((uint32_t)__bfloat16_as_ushort(l1) << 16) | __bfloat16_as_ushort(l0);
        uint32_t sw = sw128(r * 128 + w * 4);
        *(uint32_t*)(smem + OFF_SW_HI + sw) = hw;
        *(uint32_t*)(smem + OFF_SW_LO + sw) = lw;
    }

    // ---- prologue: s_j + quantum for this warp's 128 j ----
    const float agg_i = g_AG[i];
    const float hi_l  = g_Hh[i * LD + lane];
    const float zi    = g_CI[i * LD + lane] + bc[lane];
    const float cs_i  = g_CS[i * LD + lane];
    const float sn_i  = g_SN[i * LD + lane];

    float qacc = 0.0f, ssum = 0.0f;

#pragma unroll 1
    for (int v0 = 0; v0 < 128; v0 += 4) {
        const int j0p = warp * 128 + v0;
        float e[4], d2[4];
#pragma unroll
        for (int u = 0; u < 4; u++) {
            float hj = g_Hh[(j0p + u) * LD + lane];
            e[u] = hj - hi_l;
            d2[u] = e[u] * e[u];
        }
#pragma unroll
        for (int o = 16; o > 0; o >>= 1) {
#pragma unroll
            for (int u = 0; u < 4; u++)
                d2[u] += __shfl_xor_sync(0xffffffffu, d2[u], o);
        }
        float sv[4];
#pragma unroll
        for (int u = 0; u < 4; u++) {
            int j = j0p + u;
            float s = fminf(rsqrtf(d2[u]), 2.0f) * agg_i;
            if (j == i) s = 0.0f;
            sv[u] = s;
            ssum += s;
            float pf = cs_i * g_CS[j * LD + lane] + sn_i * g_SN[j * LD + lane];
            float z  = zi + g_CJ[j * LD + lane];
            float coh = __fdividef(1.0f, 1.0f + __expf(-z));
            qacc += pf * coh * e[u];
        }
        if (lane == 0)
            *(float4*)(sS + j0p) = make_float4(sv[0], sv[1], sv[2], sv[3]);
    }

    const float ak0 = g_A[i * HD + 2 * lane];
    const float ak1 = g_A[i * HD + 2 * lane + 1];

    const int jb = (warp & 1) * 64;
    const int rb = (warp >> 1) * 16;

    uint32_t rowAoff[4], swA[4];
#pragma unroll
    for (int mt = 0; mt < 4; mt++) {
        uint32_t ro = (uint32_t)(jb + mt * 16 + (lane & 15)) * 128;
        rowAoff[mt] = ro;
        swA[mt] = (ro >> 3) & 0x70;
    }
    const uint32_t kaddA = (uint32_t)(lane & 16);
    const uint32_t rowBoff = (uint32_t)(rb + (lane & 7) + ((lane & 16) >> 1)) * 128;
    const uint32_t swB = (rowBoff >> 3) & 0x70;
    const uint32_t kaddB = (uint32_t)((lane & 8) << 1);

    float bi2v[4];
#pragma unroll
    for (int nt = 0; nt < 2; nt++)
#pragma unroll
        for (int cb = 0; cb < 2; cb++)
            bi2v[nt * 2 + cb] = bi2[rb + nt * 8 + (lane & 3) * 2 + cb];

    float colacc[4] = {0.f, 0.f, 0.f, 0.f};

    __syncthreads();   // W tiles + all sS visible

    // =================== main loop over 8 j-tiles ===================
    for (int t = 0; t < 8; t++) {
        const int j0 = t * 128;
        const float* sTile = sS + j0;

#pragma unroll 2
        for (int v = 0; v < 16; v++) {
            int jl = warp * 16 + v;
            float2 b2 = *(const float2*)(g_Bv + (j0 + jl) * HD + 2 * lane);
            float x0 = tanh_fast(ak0 + b2.x);
            float x1v = tanh_fast(ak1 + b2.y);
            __nv_bfloat16 h0 = __float2bfloat16(x0), h1 = __float2bfloat16(x1v);
            __nv_bfloat16 l0 = __float2bfloat16(x0 - __bfloat162float(h0));
            __nv_bfloat16 l1 = __float2bfloat16(x1v - __bfloat162float(h1));
            uint32_t hw = ((uint32_t)__bfloat16_as_ushort(h1) << 16) | __bfloat16_as_ushort(h0);
            uint32_t lw = ((uint32_t)__bfloat16_as_ushort(l1) << 16) | __bfloat16_as_ushort(l0);
            uint32_t sw = sw128((uint32_t)jl * 128 + lane * 4);
            *(uint32_t*)(smem + OFF_SX_HI + sw) = hw;
            *(uint32_t*)(smem + OFF_SX_LO + sw) = lw;
        }
        __syncthreads();

        float acc[4][2][4];
#pragma unroll
        for (int mt = 0; mt < 4; mt++)
#pragma unroll
            for (int nt = 0; nt < 2; nt++)
#pragma unroll
                for (int c = 0; c < 4; c++) acc[mt][nt][c] = 0.0f;

#pragma unroll
        for (int pass = 0; pass < 3; pass++) {
            const uint32_t aB = smem_base + (pass == 1 ? OFF_SX_LO : OFF_SX_HI);
            const uint32_t bB = smem_base + (pass == 2 ? OFF_SW_LO : OFF_SW_HI);
#pragma unroll
            for (int ks = 0; ks < 4; ks++) {
                const uint32_t kb = ks * 32;
                uint32_t b0, b1, b2r, b3;
                LDM4(b0, b1, b2r, b3, bB + rowBoff + ((kb + kaddB) ^ swB));
#pragma unroll
                for (int mt = 0; mt < 4; mt++) {
                    uint32_t a0, a1, a2, a3;
                    LDM4(a0, a1, a2, a3, aB + rowAoff[mt] + ((kb + kaddA) ^ swA[mt]));
                    MMA_BF16(acc[mt][0], a0, a1, a2, a3, b0, b1);
                    MMA_BF16(acc[mt][1], a0, a1, a2, a3, b2r, b3);
                }
            }
        }

#pragma unroll
        for (int mt = 0; mt < 4; mt++) {
            float s_a = sTile[jb + mt * 16 + (lane >> 2)];
            float s_b = sTile[jb + mt * 16 + 8 + (lane >> 2)];
#pragma unroll
            for (int nt = 0; nt < 2; nt++) {
#pragma unroll
                for (int c = 0; c < 4; c++) {
                    float x2 = tanh_fast(acc[mt][nt][c] + bi2v[nt * 2 + (c & 1)]);
                    colacc[nt * 2 + (c & 1)] += (c < 2 ? s_a : s_b) * x2;
                }
            }
        }
        __syncthreads();
    }

    // =================== final reductions ===================
#pragma unroll
    for (int q = 0; q < 4; q++) {
        float v = colacc[q];
        v += __shfl_xor_sync(0xffffffffu, v, 4);
        v += __shfl_xor_sync(0xffffffffu, v, 8);
        v += __shfl_xor_sync(0xffffffffu, v, 16);
        colacc[q] = v;
    }
    if (lane < 4) {
#pragma unroll
        for (int nt = 0; nt < 2; nt++)
#pragma unroll
            for (int cb = 0; cb < 2; cb++)
                sWRed[(warp & 1) * 64 + rb + nt * 8 + lane * 2 + cb] = colacc[nt * 2 + cb];
    }
    sQRed[warp * 32 + lane] = qacc;
    if (lane == 0) sSRed[warp] = ssum;
    __syncthreads();

    if (tid < LD) {
        float q = 0.0f;
#pragma unroll
        for (int w = 0; w < 8; w++) q += sQRed[w * 32 + tid];
        float sst = 0.0f;
#pragma unroll
        for (int w = 0; w < 8; w++) sst += sSRed[w];
        float kv = sst * bi3[tid];
#pragma unroll
        for (int r = 0; r < HD; r++)
            kv += (sWRed[r] + sWRed[64 + r]) * Wi3[tid * HD + r];
        float v = kv + q;
        out[i * (LD + 1) + tid] = SELF_SCALE * g_SELF[i * LD + tid] + INT_SCALE * v;
        float av = fabsf(v);
#pragma unroll
        for (int o = 16; o > 0; o >>= 1)
            av += __shfl_down_sync(0xffffffffu, av, o);
        if (tid == 0)
            out[i * (LD + 1) + LD] = 0.1f + 0.05f * av;
    }
}

// ---------------------------------------------------------------------------
extern "C" void kernel_launch(void* const* d_in, const int* in_sizes, int n_in,
                              void* d_out, int out_size)
{
    const float* state   = (const float*)d_in[0];
    const float* Ws1     = (const float*)d_in[1];
    const float* bs1     = (const float*)d_in[2];
    const float* Ws2     = (const float*)d_in[3];
    const float* bs2     = (const float*)d_in[4];
    const float* Ws3     = (const float*)d_in[5];
    const float* bs3     = (const float*)d_in[6];
    const float* Wi1     = (const float*)d_in[7];
    const float* bi1     = (const float*)d_in[8];
    const float* Wi2     = (const float*)d_in[9];
    const float* bi2     = (const float*)d_in[10];
    const float* Wi3     = (const float*)d_in[11];
    const float* bi3     = (const float*)d_in[12];
    const float* phase_w = (const float*)d_in[13];
    const float* Wc      = (const float*)d_in[14];
    const float* bc      = (const float*)d_in[15];
    const float* aggr    = (const float*)d_in[16];
    float* out = (float*)d_out;

    cudaFuncSetAttribute(phase1_kernel,
                         cudaFuncAttributeMaxDynamicSharedMemorySize, P1_SMEM);
    cudaFuncSetAttribute(phase2_kernel,
                         cudaFuncAttributeMaxDynamicSharedMemorySize, SMEM_TOT);

    phase1_kernel<<<128, NT, P1_SMEM>>>(state, Ws1, bs1, Ws2, bs2, Ws3, bs3,
                                        Wi1, bi1, Wc, aggr, phase_w);
    phase2_kernel<<<NB, NT, SMEM_TOT>>>(Wi2, bi2, Wi3, bi3, bc, out);
}

// round 16
// speedup vs baseline: 2.6027x; 1.0469x over previous
#include <cuda_runtime.h>
#include <cuda_bf16.h>
#include <cstdint>

#define NB 1024
#define LD 32
#define HD 64
#define NT 256
#define SELF_SCALE 0.5f
#define INT_SCALE 0.3f

// ---------------- device scratch ----------------
__device__ __align__(16) float g_A[NB * HD];     // a_i   [i][k]
__device__ __align__(16) float g_Bv[NB * HD];    // b_j   [j][k]
__device__ __align__(16) float g_CI[NB * LD];
__device__ __align__(16) float g_CJ[NB * LD];
__device__ __align__(16) float g_SELF[NB * LD];
__device__ __align__(16) float g_Hh[NB * LD];
__device__ __align__(16) float2 g_PP[NB * LD];   // (cos, sin)(ph_j * pw_l)
__device__ float g_HN[NB];                       // ||h_j||^2
__device__ float g_AG[NB];

__device__ __forceinline__ float tanh_fast(float x) {
    float e = __expf(2.0f * x);
    return 1.0f - __fdividef(2.0f, e + 1.0f);
}

__device__ __forceinline__ uint32_t smem_u32(const void* p) {
    uint32_t a;
    asm("{ .reg .u64 t; cvta.to.shared.u64 t, %1; cvt.u32.u64 %0, t; }" : "=r"(a) : "l"(p));
    return a;
}

// pack: hi-half = bf16(b), lo-half = bf16(a)
__device__ __forceinline__ uint32_t bf16x2_pack(float a, float b) {
    uint32_t r;
    asm("cvt.rn.bf16x2.f32 %0, %1, %2;" : "=r"(r) : "f"(b), "f"(a));
    return r;
}

#define LDM4(r0, r1, r2, r3, addr)                                          \
    asm volatile("ldmatrix.sync.aligned.m8n8.x4.shared.b16 {%0,%1,%2,%3}, [%4];" \
        : "=r"(r0), "=r"(r1), "=r"(r2), "=r"(r3) : "r"(addr))

#define MMA_BF16(c, a0, a1, a2, a3, b0, b1)                                 \
    asm volatile("mma.sync.aligned.m16n8k16.row.col.f32.bf16.bf16.f32 "     \
        "{%0,%1,%2,%3}, {%4,%5,%6,%7}, {%8,%9}, {%0,%1,%2,%3};"             \
        : "+f"((c)[0]), "+f"((c)[1]), "+f"((c)[2]), "+f"((c)[3])            \
        : "r"(a0), "r"(a1), "r"(a2), "r"(a3), "r"(b0), "r"(b1))

// phase2 SMEM layout (dynamic, byte offsets)
#define OFF_SW_HI 0        // Wi2 hi [r][k] 64x128B (8 KB)
#define OFF_SW_LO 8192     // Wi2 lo               (8 KB)
#define OFF_SX    16384    // x1 double buffer: 2 x (hi 16K + lo 16K) = 64 KB
#define OFF_SS    81920    // s_j for ALL 1024 j (4 KB)
#define OFF_WRED  86016    // colacc partials [2][64] (512 B)
#define OFF_QRED  86528    // quantum partials [8][32] (1 KB)
#define OFF_SRED  87552    // ssum partials [8] (32 B)
#define OFF_HI    87584    // h_i (128 B)
#define SMEM_TOT  87808

__device__ __forceinline__ uint32_t sw128(uint32_t off) {
    return off ^ ((off >> 3) & 0x70);
}

// ---------------------------------------------------------------------------
// Phase 1: 128 blocks x 256 thr, 8 nodes/block, padded transposed staging.
// ---------------------------------------------------------------------------
#define P1_S1T   0                 // [32][65]
#define P1_S2T   2080              // [64][65]
#define P1_S3T   6240              // [64][33]
#define P1_WI1T  8352              // [128][65]
#define P1_WCT   16672             // [64][33]
#define P1_BS1   18784
#define P1_BS2   18848
#define P1_BS3   18912
#define P1_BI1   18944
#define P1_H     19008             // [8][32]
#define P1_T1    19264             // [8][64]
#define P1_T2    19776             // [8][64]
#define P1_DH    20288             // [8][32]
#define P1_PH    20544             // 8
#define P1_TOT_F 20560
#define P1_SMEM  (P1_TOT_F * 4)

__global__ void __launch_bounds__(NT) phase1_kernel(
    const float* __restrict__ state,
    const float* __restrict__ Ws1, const float* __restrict__ bs1,
    const float* __restrict__ Ws2, const float* __restrict__ bs2,
    const float* __restrict__ Ws3, const float* __restrict__ bs3,
    const float* __restrict__ Wi1, const float* __restrict__ bi1,
    const float* __restrict__ Wc,  const float* __restrict__ aggr,
    const float* __restrict__ phase_w)
{
    extern __shared__ float sm[];
    const int tid = threadIdx.x;
    const int i0 = blockIdx.x * 8;

    for (int idx = tid; idx < 64 * 32; idx += NT) {
        int u = idx >> 5, l = idx & 31;
        sm[P1_S1T + l * 65 + u] = Ws1[idx];
    }
    for (int idx = tid; idx < 64 * 64; idx += NT) {
        int u = idx >> 6, k = idx & 63;
        sm[P1_S2T + k * 65 + u] = Ws2[idx];
    }
    for (int idx = tid; idx < 32 * 64; idx += NT) {
        int l = idx >> 6, k = idx & 63;
        sm[P1_S3T + k * 33 + l] = Ws3[idx];
    }
    for (int idx = tid; idx < 64 * 128; idx += NT) {
        int u = idx >> 7, c = idx & 127;
        sm[P1_WI1T + c * 65 + u] = Wi1[idx];
    }
    for (int idx = tid; idx < 32 * 64; idx += NT) {
        int l = idx >> 6, m = idx & 63;
        sm[P1_WCT + m * 33 + l] = Wc[idx];
    }
    if (tid < 64) sm[P1_BS1 + tid] = bs1[tid];
    if (tid >= 64 && tid < 128) sm[P1_BS2 + tid - 64] = bs2[tid - 64];
    if (tid >= 128 && tid < 160) sm[P1_BS3 + tid - 128] = bs3[tid - 128];
    if (tid >= 160 && tid < 224) sm[P1_BI1 + tid - 160] = bi1[tid - 160];

    for (int idx = tid; idx < 8 * 33; idx += NT) {
        int n = idx / 33, c = idx % 33;
        float v = state[(i0 + n) * 33 + c];
        if (c < 32) sm[P1_H + n * 32 + c] = v;
        else        sm[P1_PH + n] = v;
    }
    __syncthreads();

    const int u = tid & 63;
    const int nq = tid >> 6;
    const int l5 = tid & 31;
    const int n5 = tid >> 5;

#pragma unroll
    for (int g = 0; g < 2; g++) {
        int n = g * 4 + nq;
        float acc = sm[P1_BS1 + u];
#pragma unroll
        for (int l = 0; l < 32; l++)
            acc += sm[P1_S1T + l * 65 + u] * sm[P1_H + n * 32 + l];
        sm[P1_T1 + n * 64 + u] = tanhf(acc);
    }
    __syncthreads();

#pragma unroll
    for (int g = 0; g < 2; g++) {
        int n = g * 4 + nq;
        float acc = sm[P1_BS2 + u];
#pragma unroll
        for (int k = 0; k < 64; k++)
            acc += sm[P1_S2T + k * 65 + u] * sm[P1_T1 + n * 64 + k];
        sm[P1_T2 + n * 64 + u] = tanhf(acc);
    }
    __syncthreads();

    {
        int n = n5;
        float acc = sm[P1_BS3 + l5];
#pragma unroll
        for (int k = 0; k < 64; k++)
            acc += sm[P1_S3T + k * 33 + l5] * sm[P1_T2 + n * 64 + k];
        sm[P1_DH + n * 32 + l5] = acc;
        g_SELF[(i0 + n) * 32 + l5] = acc;
        float hv = sm[P1_H + n * 32 + l5];
        g_Hh[(i0 + n) * 32 + l5] = hv;
        // ||h||^2 via warp butterfly (cheap; once per node)
        float hn = hv * hv;
#pragma unroll
        for (int o = 16; o > 0; o >>= 1)
            hn += __shfl_xor_sync(0xffffffffu, hn, o);
        if (l5 == 0) g_HN[i0 + n] = hn;
    }
    __syncthreads();

#pragma unroll
    for (int g = 0; g < 2; g++) {
        int n = g * 4 + nq;
        float a = 0.0f, b = sm[P1_BI1 + u];
#pragma unroll
        for (int l = 0; l < 32; l++) {
            float hv = sm[P1_H + n * 32 + l];
            float dv = sm[P1_DH + n * 32 + l];
            a += sm[P1_WI1T + l * 65 + u] * hv + sm[P1_WI1T + (64 + l) * 65 + u] * dv;
            b += sm[P1_WI1T + (32 + l) * 65 + u] * hv + sm[P1_WI1T + (96 + l) * 65 + u] * dv;
        }
        g_A[(i0 + n) * 64 + u] = a;
        g_Bv[(i0 + n) * 64 + u] = b;
    }

    {
        int n = n5;
        float ci = 0.0f, cj = 0.0f;
#pragma unroll
        for (int m = 0; m < 32; m++) {
            float hv = sm[P1_H + n * 32 + m];
            ci += sm[P1_WCT + m * 33 + l5] * hv;
            cj += sm[P1_WCT + (32 + m) * 33 + l5] * hv;
        }
        g_CI[(i0 + n) * 32 + l5] = ci;
        g_CJ[(i0 + n) * 32 + l5] = cj;
        float cs, sn;
        sincosf(sm[P1_PH + n] * phase_w[l5], &sn, &cs);
        g_PP[(i0 + n) * 32 + l5] = make_float2(cs, sn);
    }
    if (tid < 8)
        g_AG[i0 + tid] = 1.0f / (1.0f + expf(-aggr[i0 + tid]));
}

// ---------------------------------------------------------------------------
// Phase 2 (fused): quantum (lane=l, no shfl) + s via norm identity (thread
// per j, no shfl) + double-buffered HMMA split-bf16 mainloop (1 sync/tile).
// ---------------------------------------------------------------------------
__global__ void __launch_bounds__(NT, 2) phase2_kernel(
    const float* __restrict__ Wi2, const float* __restrict__ bi2,
    const float* __restrict__ Wi3, const float* __restrict__ bi3,
    const float* __restrict__ bc,  float* __restrict__ out)
{
    extern __shared__ char smem[];
    const uint32_t smem_base = smem_u32(smem);
    const int i = blockIdx.x;
    const int tid = threadIdx.x;
    const int lane = tid & 31;
    const int warp = tid >> 5;

    float* sS    = (float*)(smem + OFF_SS);
    float* sWRed = (float*)(smem + OFF_WRED);
    float* sQRed = (float*)(smem + OFF_QRED);
    float* sSRed = (float*)(smem + OFF_SRED);
    float* sHi   = (float*)(smem + OFF_HI);

    // ---- stage Wi2 hi/lo into swizzled SMEM [r][k] ----
    for (int idx = tid; idx < HD * 32; idx += NT) {
        int r = idx >> 5, w = idx & 31;
        float2 v = *(const float2*)(Wi2 + r * HD + 2 * w);
        uint32_t hw = bf16x2_pack(v.x, v.y);
        float h0f = __uint_as_float(hw << 16);
        float h1f = __uint_as_float(hw & 0xFFFF0000u);
        uint32_t lw = bf16x2_pack(v.x - h0f, v.y - h1f);
        uint32_t sw = sw128(r * 128 + w * 4);
        *(uint32_t*)(smem + OFF_SW_HI + sw) = hw;
        *(uint32_t*)(smem + OFF_SW_LO + sw) = lw;
    }
    if (tid < 32) sHi[tid] = g_Hh[i * LD + tid];
    __syncthreads();

    // ---- part A: quantum term (warp owns 128 j, lane = l; no shfl) ----
    const float hi_l = sHi[lane];
    const float zi   = g_CI[i * LD + lane] + bc[lane];
    const float2 ppi = g_PP[i * LD + lane];

    float qacc = 0.0f;
#pragma unroll 1
    for (int v0 = 0; v0 < 128; v0 += 4) {
#pragma unroll
        for (int u = 0; u < 4; u++) {
            int j = warp * 128 + v0 + u;
            float e = g_Hh[j * LD + lane] - hi_l;
            float2 ppj = g_PP[j * LD + lane];
            float pf = ppi.x * ppj.x + ppi.y * ppj.y;
            float z  = zi + g_CJ[j * LD + lane];
            float coh = __fdividef(1.0f, 1.0f + __expf(-z));
            qacc += pf * coh * e;
        }
    }

    // ---- part B: s_j via d2 = ni + nj - 2 dot (thread per j; no shfl) ----
    const float agg_i = g_AG[i];
    const float ni = g_HN[i];
    float ssum = 0.0f;
    const float4* hi4 = (const float4*)sHi;
#pragma unroll
    for (int rep = 0; rep < 4; rep++) {
        int j = rep * 256 + tid;
        const float4* hj4 = (const float4*)(g_Hh + j * LD);
        float dot = 0.0f;
#pragma unroll
        for (int q = 0; q < 8; q++) {
            float4 a = hi4[q], b = hj4[q];
            dot += a.x * b.x + a.y * b.y + a.z * b.z + a.w * b.w;
        }
        float d2 = ni + g_HN[j] - 2.0f * dot;
        float s = fminf(rsqrtf(d2), 2.0f) * agg_i;   // NaN/Inf -> 2 via fminf
        if (j == i) s = 0.0f;
        sS[j] = s;
        ssum += s;
    }

    // ---- MMA constants ----
    const float ak0 = g_A[i * HD + 2 * lane];
    const float ak1 = g_A[i * HD + 2 * lane + 1];

    const int jb = (warp & 1) * 64;
    const int rb = (warp >> 1) * 16;

    uint32_t rowAoff[4], swA[4];
#pragma unroll
    for (int mt = 0; mt < 4; mt++) {
        uint32_t ro = (uint32_t)(jb + mt * 16 + (lane & 15)) * 128;
        rowAoff[mt] = ro;
        swA[mt] = (ro >> 3) & 0x70;
    }
    const uint32_t kaddA = (uint32_t)(lane & 16);
    const uint32_t rowBoff = (uint32_t)(rb + (lane & 7) + ((lane & 16) >> 1)) * 128;
    const uint32_t swB = (rowBoff >> 3) & 0x70;
    const uint32_t kaddB = (uint32_t)((lane & 8) << 1);

    float bi2v[4];
#pragma unroll
    for (int nt = 0; nt < 2; nt++)
#pragma unroll
        for (int cb = 0; cb < 2; cb++)
            bi2v[nt * 2 + cb] = bi2[rb + nt * 8 + (lane & 3) * 2 + cb];

    float colacc[4] = {0.f, 0.f, 0.f, 0.f};

    // ---- produce tile 0 into buffer 0 ----
    {
        char* bh = smem + OFF_SX;            // buf 0 hi
        char* bl = bh + 16384;               // buf 0 lo
#pragma unroll 2
        for (int v = 0; v < 16; v++) {
            int jl = warp * 16 + v;
            float2 b2 = *(const float2*)(g_Bv + jl * HD + 2 * lane);
            float x0 = tanh_fast(ak0 + b2.x);
            float x1v = tanh_fast(ak1 + b2.y);
            uint32_t hw = bf16x2_pack(x0, x1v);
            float h0f = __uint_as_float(hw << 16);
            float h1f = __uint_as_float(hw & 0xFFFF0000u);
            uint32_t lw = bf16x2_pack(x0 - h0f, x1v - h1f);
            uint32_t sw = sw128((uint32_t)jl * 128 + lane * 4);
            *(uint32_t*)(bh + sw) = hw;
            *(uint32_t*)(bl + sw) = lw;
        }
    }
    __syncthreads();   // sS complete + buf0 visible

    // =================== main loop: 1 sync per tile ===================
    for (int t = 0; t < 8; t++) {
        // produce tile t+1 into the other buffer (overlaps MMA of tile t)
        if (t < 7) {
            char* bh = smem + OFF_SX + ((t + 1) & 1) * 32768;
            char* bl = bh + 16384;
            const int j0n = (t + 1) * 128;
#pragma unroll 2
            for (int v = 0; v < 16; v++) {
                int jl = warp * 16 + v;
                float2 b2 = *(const float2*)(g_Bv + (j0n + jl) * HD + 2 * lane);
                float x0 = tanh_fast(ak0 + b2.x);
                float x1v = tanh_fast(ak1 + b2.y);
                uint32_t hw = bf16x2_pack(x0, x1v);
                float h0f = __uint_as_float(hw << 16);
                float h1f = __uint_as_float(hw & 0xFFFF0000u);
                uint32_t lw = bf16x2_pack(x0 - h0f, x1v - h1f);
                uint32_t sw = sw128((uint32_t)jl * 128 + lane * 4);
                *(uint32_t*)(bh + sw) = hw;
                *(uint32_t*)(bl + sw) = lw;
            }
        }

        // MMA on buffer t&1
        float acc[4][2][4];
#pragma unroll
        for (int mt = 0; mt < 4; mt++)
#pragma unroll
            for (int nt = 0; nt < 2; nt++)
#pragma unroll
                for (int c = 0; c < 4; c++) acc[mt][nt][c] = 0.0f;

        const uint32_t bufb = smem_base + OFF_SX + (t & 1) * 32768;
#pragma unroll
        for (int pass = 0; pass < 3; pass++) {
            const uint32_t aB = bufb + (pass == 1 ? 16384 : 0);
            const uint32_t bB = smem_base + (pass == 2 ? OFF_SW_LO : OFF_SW_HI);
#pragma unroll
            for (int ks = 0; ks < 4; ks++) {
                const uint32_t kb = ks * 32;
                uint32_t b0, b1, b2r, b3;
                LDM4(b0, b1, b2r, b3, bB + rowBoff + ((kb + kaddB) ^ swB));
#pragma unroll
                for (int mt = 0; mt < 4; mt++) {
                    uint32_t a0, a1, a2, a3;
                    LDM4(a0, a1, a2, a3, aB + rowAoff[mt] + ((kb + kaddA) ^ swA[mt]));
                    MMA_BF16(acc[mt][0], a0, a1, a2, a3, b0, b1);
                    MMA_BF16(acc[mt][1], a0, a1, a2, a3, b2r, b3);
                }
            }
        }

        // epilogue: tanh, weight by s_j, fold into colacc
        const float* sTile = sS + t * 128;
#pragma unroll
        for (int mt = 0; mt < 4; mt++) {
            float s_a = sTile[jb + mt * 16 + (lane >> 2)];
            float s_b = sTile[jb + mt * 16 + 8 + (lane >> 2)];
#pragma unroll
            for (int nt = 0; nt < 2; nt++) {
#pragma unroll
                for (int c = 0; c < 4; c++) {
                    float x2 = tanh_fast(acc[mt][nt][c] + bi2v[nt * 2 + (c & 1)]);
                    colacc[nt * 2 + (c & 1)] += (c < 2 ? s_a : s_b) * x2;
                }
            }
        }
        __syncthreads();   // buf (t+1) ready; buf t free for produce(t+2)
    }

    // =================== final reductions ===================
#pragma unroll
    for (int q = 0; q < 4; q++) {
        float v = colacc[q];
        v += __shfl_xor_sync(0xffffffffu, v, 4);
        v += __shfl_xor_sync(0xffffffffu, v, 8);
        v += __shfl_xor_sync(0xffffffffu, v, 16);
        colacc[q] = v;
    }
    if (lane < 4) {
#pragma unroll
        for (int nt = 0; nt < 2; nt++)
#pragma unroll
            for (int cb = 0; cb < 2; cb++)
                sWRed[(warp & 1) * 64 + rb + nt * 8 + lane * 2 + cb] = colacc[nt * 2 + cb];
    }
    sQRed[warp * 32 + lane] = qacc;
    // ssum: per-thread partial -> warp reduce -> per-warp slot
    {
        float v = ssum;
#pragma unroll
        for (int o = 16; o > 0; o >>= 1)
            v += __shfl_xor_sync(0xffffffffu, v, o);
        if (lane == 0) sSRed[warp] = v;
    }
    __syncthreads();

    if (tid < LD) {
        float q = 0.0f;
#pragma unroll
        for (int w = 0; w < 8; w++) q += sQRed[w * 32 + tid];
        float sst = 0.0f;
#pragma unroll
        for (int w = 0; w < 8; w++) sst += sSRed[w];
        float kv = sst * bi3[tid];
#pragma unroll
        for (int r = 0; r < HD; r++)
            kv += (sWRed[r] + sWRed[64 + r]) * Wi3[tid * HD + r];
        float v = kv + q;
        out[i * (LD + 1) + tid] = SELF_SCALE * g_SELF[i * LD + tid] + INT_SCALE * v;
        float av = fabsf(v);
#pragma unroll
        for (int o = 16; o > 0; o >>= 1)
            av += __shfl_down_sync(0xffffffffu, av, o);
        if (tid == 0)
            out[i * (LD + 1) + LD] = 0.1f + 0.05f * av;
    }
}

// ---------------------------------------------------------------------------
extern "C" void kernel_launch(void* const* d_in, const int* in_sizes, int n_in,
                              void* d_out, int out_size)
{
    const float* state   = (const float*)d_in[0];
    const float* Ws1     = (const float*)d_in[1];
    const float* bs1     = (const float*)d_in[2];
    const float* Ws2     = (const float*)d_in[3];
    const float* bs2     = (const float*)d_in[4];
    const float* Ws3     = (const float*)d_in[5];
    const float* bs3     = (const float*)d_in[6];
    const float* Wi1     = (const float*)d_in[7];
    const float* bi1     = (const float*)d_in[8];
    const float* Wi2     = (const float*)d_in[9];
    const float* bi2     = (const float*)d_in[10];
    const float* Wi3     = (const float*)d_in[11];
    const float* bi3     = (const float*)d_in[12];
    const float* phase_w = (const float*)d_in[13];
    const float* Wc      = (const float*)d_in[14];
    const float* bc      = (const float*)d_in[15];
    const float* aggr    = (const float*)d_in[16];
    float* out = (float*)d_out;

    cudaFuncSetAttribute(phase1_kernel,
                         cudaFuncAttributeMaxDynamicSharedMemorySize, P1_SMEM);
    cudaFuncSetAttribute(phase2_kernel,
                         cudaFuncAttributeMaxDynamicSharedMemorySize, SMEM_TOT);

    phase1_kernel<<<128, NT, P1_SMEM>>>(state, Ws1, bs1, Ws2, bs2, Ws3, bs3,
                                        Wi1, bi1, Wc, aggr, phase_w);
    phase2_kernel<<<NB, NT, SMEM_TOT>>>(Wi2, bi2, Wi3, bi3, bc, out);
}

// round 17
// speedup vs baseline: 3.0973x; 1.1900x over previous
#include <cuda_runtime.h>
#include <cuda_bf16.h>
#include <cstdint>

#define NB 1024
#define LD 32
#define HD 64
#define NT 256
#define SELF_SCALE 0.5f
#define INT_SCALE 0.3f

// ---------------- device scratch ----------------
__device__ __align__(16) float g_A[NB * HD];     // a_i   [i][k]
__device__ __align__(16) float g_Bv[NB * HD];    // b_j   [j][k]
__device__ __align__(16) float g_CI[NB * LD];
__device__ __align__(16) float g_CJ[NB * LD];
__device__ __align__(16) float g_SELF[NB * LD];
__device__ __align__(16) float g_Hh[NB * LD];
__device__ __align__(16) float2 g_PP[NB * LD];   // (cos, sin)(ph_j * pw_l)
__device__ float g_HN[NB];                       // ||h_j||^2
__device__ float g_AG[NB];

__device__ __forceinline__ float tanh_fast(float x) {
    float e = __expf(2.0f * x);
    return 1.0f - __fdividef(2.0f, e + 1.0f);
}

__device__ __forceinline__ uint32_t smem_u32(const void* p) {
    uint32_t a;
    asm("{ .reg .u64 t; cvta.to.shared.u64 t, %1; cvt.u32.u64 %0, t; }" : "=r"(a) : "l"(p));
    return a;
}

// pack: hi-half = bf16(b), lo-half = bf16(a)
__device__ __forceinline__ uint32_t bf16x2_pack(float a, float b) {
    uint32_t r;
    asm("cvt.rn.bf16x2.f32 %0, %1, %2;" : "=r"(r) : "f"(b), "f"(a));
    return r;
}

#define LDM4(r0, r1, r2, r3, addr)                                          \
    asm volatile("ldmatrix.sync.aligned.m8n8.x4.shared.b16 {%0,%1,%2,%3}, [%4];" \
        : "=r"(r0), "=r"(r1), "=r"(r2), "=r"(r3) : "r"(addr))

#define MMA_BF16(c, a0, a1, a2, a3, b0, b1)                                 \
    asm volatile("mma.sync.aligned.m16n8k16.row.col.f32.bf16.bf16.f32 "     \
        "{%0,%1,%2,%3}, {%4,%5,%6,%7}, {%8,%9}, {%0,%1,%2,%3};"             \
        : "+f"((c)[0]), "+f"((c)[1]), "+f"((c)[2]), "+f"((c)[3])            \
        : "r"(a0), "r"(a1), "r"(a2), "r"(a3), "r"(b0), "r"(b1))

// phase2 SMEM layout (dynamic, byte offsets)
#define OFF_SW_HI 0        // Wi2 hi [r][k] 64x128B (8 KB)
#define OFF_SW_LO 8192     // Wi2 lo               (8 KB)
#define OFF_SX    16384    // x1 double buffer: 2 x (hi 16K + lo 16K) = 64 KB
#define OFF_SS    81920    // s_j for ALL 1024 j (4 KB)
#define OFF_WRED  86016    // colacc partials [2][64] (512 B)
#define OFF_QRED  86528    // quantum partials [8][32] (1 KB)
#define OFF_SRED  87552    // ssum partials [8] (32 B)
#define OFF_HI    87584    // h_i (128 B)
#define SMEM_TOT  87808

__device__ __forceinline__ uint32_t sw128(uint32_t off) {
    return off ^ ((off >> 3) & 0x70);
}

// ---------------------------------------------------------------------------
// Phase 1: 128 blocks x 256 thr, 8 nodes/block, padded transposed staging.
// ---------------------------------------------------------------------------
#define P1_S1T   0                 // [32][65]
#define P1_S2T   2080              // [64][65]
#define P1_S3T   6240              // [64][33]
#define P1_WI1T  8352              // [128][65]
#define P1_WCT   16672             // [64][33]
#define P1_BS1   18784
#define P1_BS2   18848
#define P1_BS3   18912
#define P1_BI1   18944
#define P1_H     19008             // [8][32]
#define P1_T1    19264             // [8][64]
#define P1_T2    19776             // [8][64]
#define P1_DH    20288             // [8][32]
#define P1_PH    20544             // 8
#define P1_TOT_F 20560
#define P1_SMEM  (P1_TOT_F * 4)

__global__ void __launch_bounds__(NT) phase1_kernel(
    const float* __restrict__ state,
    const float* __restrict__ Ws1, const float* __restrict__ bs1,
    const float* __restrict__ Ws2, const float* __restrict__ bs2,
    const float* __restrict__ Ws3, const float* __restrict__ bs3,
    const float* __restrict__ Wi1, const float* __restrict__ bi1,
    const float* __restrict__ Wc,  const float* __restrict__ aggr,
    const float* __restrict__ phase_w)
{
    extern __shared__ float sm[];
    const int tid = threadIdx.x;
    const int i0 = blockIdx.x * 8;

    for (int idx = tid; idx < 64 * 32; idx += NT) {
        int u = idx >> 5, l = idx & 31;
        sm[P1_S1T + l * 65 + u] = Ws1[idx];
    }
    for (int idx = tid; idx < 64 * 64; idx += NT) {
        int u = idx >> 6, k = idx & 63;
        sm[P1_S2T + k * 65 + u] = Ws2[idx];
    }
    for (int idx = tid; idx < 32 * 64; idx += NT) {
        int l = idx >> 6, k = idx & 63;
        sm[P1_S3T + k * 33 + l] = Ws3[idx];
    }
    for (int idx = tid; idx < 64 * 128; idx += NT) {
        int u = idx >> 7, c = idx & 127;
        sm[P1_WI1T + c * 65 + u] = Wi1[idx];
    }
    for (int idx = tid; idx < 32 * 64; idx += NT) {
        int l = idx >> 6, m = idx & 63;
        sm[P1_WCT + m * 33 + l] = Wc[idx];
    }
    if (tid < 64) sm[P1_BS1 + tid] = bs1[tid];
    if (tid >= 64 && tid < 128) sm[P1_BS2 + tid - 64] = bs2[tid - 64];
    if (tid >= 128 && tid < 160) sm[P1_BS3 + tid - 128] = bs3[tid - 128];
    if (tid >= 160 && tid < 224) sm[P1_BI1 + tid - 160] = bi1[tid - 160];

    for (int idx = tid; idx < 8 * 33; idx += NT) {
        int n = idx / 33, c = idx % 33;
        float v = state[(i0 + n) * 33 + c];
        if (c < 32) sm[P1_H + n * 32 + c] = v;
        else        sm[P1_PH + n] = v;
    }
    __syncthreads();

    const int u = tid & 63;
    const int nq = tid >> 6;
    const int l5 = tid & 31;
    const int n5 = tid >> 5;

#pragma unroll
    for (int g = 0; g < 2; g++) {
        int n = g * 4 + nq;
        float acc = sm[P1_BS1 + u];
#pragma unroll
        for (int l = 0; l < 32; l++)
            acc += sm[P1_S1T + l * 65 + u] * sm[P1_H + n * 32 + l];
        sm[P1_T1 + n * 64 + u] = tanhf(acc);
    }
    __syncthreads();

#pragma unroll
    for (int g = 0; g < 2; g++) {
        int n = g * 4 + nq;
        float acc = sm[P1_BS2 + u];
#pragma unroll
        for (int k = 0; k < 64; k++)
            acc += sm[P1_S2T + k * 65 + u] * sm[P1_T1 + n * 64 + k];
        sm[P1_T2 + n * 64 + u] = tanhf(acc);
    }
    __syncthreads();

    {
        int n = n5;
        float acc = sm[P1_BS3 + l5];
#pragma unroll
        for (int k = 0; k < 64; k++)
            acc += sm[P1_S3T + k * 33 + l5] * sm[P1_T2 + n * 64 + k];
        sm[P1_DH + n * 32 + l5] = acc;
        g_SELF[(i0 + n) * 32 + l5] = acc;
        float hv = sm[P1_H + n * 32 + l5];
        g_Hh[(i0 + n) * 32 + l5] = hv;
        float hn = hv * hv;
#pragma unroll
        for (int o = 16; o > 0; o >>= 1)
            hn += __shfl_xor_sync(0xffffffffu, hn, o);
        if (l5 == 0) g_HN[i0 + n] = hn;
    }
    __syncthreads();

#pragma unroll
    for (int g = 0; g < 2; g++) {
        int n = g * 4 + nq;
        float a = 0.0f, b = sm[P1_BI1 + u];
#pragma unroll
        for (int l = 0; l < 32; l++) {
            float hv = sm[P1_H + n * 32 + l];
            float dv = sm[P1_DH + n * 32 + l];
            a += sm[P1_WI1T + l * 65 + u] * hv + sm[P1_WI1T + (64 + l) * 65 + u] * dv;
            b += sm[P1_WI1T + (32 + l) * 65 + u] * hv + sm[P1_WI1T + (96 + l) * 65 + u] * dv;
        }
        g_A[(i0 + n) * 64 + u] = a;
        g_Bv[(i0 + n) * 64 + u] = b;
    }

    {
        int n = n5;
        float ci = 0.0f, cj = 0.0f;
#pragma unroll
        for (int m = 0; m < 32; m++) {
            float hv = sm[P1_H + n * 32 + m];
            ci += sm[P1_WCT + m * 33 + l5] * hv;
            cj += sm[P1_WCT + (32 + m) * 33 + l5] * hv;
        }
        g_CI[(i0 + n) * 32 + l5] = ci;
        g_CJ[(i0 + n) * 32 + l5] = cj;
        float cs, sn;
        sincosf(sm[P1_PH + n] * phase_w[l5], &sn, &cs);
        g_PP[(i0 + n) * 32 + l5] = make_float2(cs, sn);
    }
    if (tid < 8)
        g_AG[i0 + tid] = 1.0f / (1.0f + expf(-aggr[i0 + tid]));
}

// ---------------------------------------------------------------------------
// Phase 2 (fused): quantum + s prologue, double-buffered split-bf16 HMMA
// with fused per-ks MMA loop (A-hi/B fragments loaded once, 40 LDM4/tile).
// ---------------------------------------------------------------------------
__global__ void __launch_bounds__(NT, 2) phase2_kernel(
    const float* __restrict__ Wi2, const float* __restrict__ bi2,
    const float* __restrict__ Wi3, const float* __restrict__ bi3,
    const float* __restrict__ bc,  float* __restrict__ out)
{
    extern __shared__ char smem[];
    const uint32_t smem_base = smem_u32(smem);
    const int i = blockIdx.x;
    const int tid = threadIdx.x;
    const int lane = tid & 31;
    const int warp = tid >> 5;

    float* sS    = (float*)(smem + OFF_SS);
    float* sWRed = (float*)(smem + OFF_WRED);
    float* sQRed = (float*)(smem + OFF_QRED);
    float* sSRed = (float*)(smem + OFF_SRED);
    float* sHi   = (float*)(smem + OFF_HI);

    // ---- stage Wi2 hi/lo into swizzled SMEM [r][k] ----
    for (int idx = tid; idx < HD * 32; idx += NT) {
        int r = idx >> 5, w = idx & 31;
        float2 v = *(const float2*)(Wi2 + r * HD + 2 * w);
        uint32_t hw = bf16x2_pack(v.x, v.y);
        float h0f = __uint_as_float(hw << 16);
        float h1f = __uint_as_float(hw & 0xFFFF0000u);
        uint32_t lw = bf16x2_pack(v.x - h0f, v.y - h1f);
        uint32_t sw = sw128(r * 128 + w * 4);
        *(uint32_t*)(smem + OFF_SW_HI + sw) = hw;
        *(uint32_t*)(smem + OFF_SW_LO + sw) = lw;
    }
    if (tid < 32) sHi[tid] = g_Hh[i * LD + tid];
    __syncthreads();

    // ---- part A: quantum term (warp owns 128 j, lane = l; no shfl) ----
    const float hi_l = sHi[lane];
    const float zi   = g_CI[i * LD + lane] + bc[lane];
    const float2 ppi = g_PP[i * LD + lane];

    float qacc = 0.0f;
#pragma unroll 1
    for (int v0 = 0; v0 < 128; v0 += 4) {
        float ee[4], zz[4]; float2 pj[4];
#pragma unroll
        for (int u = 0; u < 4; u++) {
            int j = warp * 128 + v0 + u;
            ee[u] = g_Hh[j * LD + lane] - hi_l;
            pj[u] = g_PP[j * LD + lane];
            zz[u] = zi + g_CJ[j * LD + lane];
        }
#pragma unroll
        for (int u = 0; u < 4; u++) {
            float pf = ppi.x * pj[u].x + ppi.y * pj[u].y;
            float coh = __fdividef(1.0f, 1.0f + __expf(-zz[u]));
            qacc += pf * coh * ee[u];
        }
    }

    // ---- part B: s_j via d2 = ni + nj - 2 dot (thread per j; no shfl) ----
    const float agg_i = g_AG[i];
    const float ni = g_HN[i];
    float ssum = 0.0f;
    const float4* hi4 = (const float4*)sHi;
#pragma unroll
    for (int rep = 0; rep < 4; rep++) {
        int j = rep * 256 + tid;
        const float4* hj4 = (const float4*)(g_Hh + j * LD);
        float dot = 0.0f;
#pragma unroll
        for (int q = 0; q < 8; q++) {
            float4 a = hi4[q], b = hj4[q];
            dot += a.x * b.x + a.y * b.y + a.z * b.z + a.w * b.w;
        }
        float d2 = ni + g_HN[j] - 2.0f * dot;
        float s = fminf(rsqrtf(d2), 2.0f) * agg_i;   // NaN/Inf -> 2 via fminf
        if (j == i) s = 0.0f;
        sS[j] = s;
        ssum += s;
    }

    // ---- MMA constants ----
    const float ak0 = g_A[i * HD + 2 * lane];
    const float ak1 = g_A[i * HD + 2 * lane + 1];

    const int jb = (warp & 1) * 64;
    const int rb = (warp >> 1) * 16;

    uint32_t rowAoff[4], swA[4];
#pragma unroll
    for (int mt = 0; mt < 4; mt++) {
        uint32_t ro = (uint32_t)(jb + mt * 16 + (lane & 15)) * 128;
        rowAoff[mt] = ro;
        swA[mt] = (ro >> 3) & 0x70;
    }
    const uint32_t kaddA = (uint32_t)(lane & 16);
    const uint32_t rowBoff = (uint32_t)(rb + (lane & 7) + ((lane & 16) >> 1)) * 128;
    const uint32_t swB = (rowBoff >> 3) & 0x70;
    const uint32_t kaddB = (uint32_t)((lane & 8) << 1);

    float bi2v[4];
#pragma unroll
    for (int nt = 0; nt < 2; nt++)
#pragma unroll
        for (int cb = 0; cb < 2; cb++)
            bi2v[nt * 2 + cb] = bi2[rb + nt * 8 + (lane & 3) * 2 + cb];

    float colacc[4] = {0.f, 0.f, 0.f, 0.f};

    // ---- produce tile 0 into buffer 0 (4-wide load batching) ----
    {
        char* bh = smem + OFF_SX;
        char* bl = bh + 16384;
#pragma unroll
        for (int vb = 0; vb < 16; vb += 4) {
            float2 b2[4];
#pragma unroll
            for (int u = 0; u < 4; u++)
                b2[u] = *(const float2*)(g_Bv + (warp * 16 + vb + u) * HD + 2 * lane);
#pragma unroll
            for (int u = 0; u < 4; u++) {
                int jl = warp * 16 + vb + u;
                float x0 = tanh_fast(ak0 + b2[u].x);
                float x1v = tanh_fast(ak1 + b2[u].y);
                uint32_t hw = bf16x2_pack(x0, x1v);
                float h0f = __uint_as_float(hw << 16);
                float h1f = __uint_as_float(hw & 0xFFFF0000u);
                uint32_t lw = bf16x2_pack(x0 - h0f, x1v - h1f);
                uint32_t sw = sw128((uint32_t)jl * 128 + lane * 4);
                *(uint32_t*)(bh + sw) = hw;
                *(uint32_t*)(bl + sw) = lw;
            }
        }
    }
    __syncthreads();   // sS complete + buf0 visible

    // =================== main loop: 1 sync per tile ===================
    for (int t = 0; t < 8; t++) {
        // produce tile t+1 into the other buffer (overlaps MMA of tile t)
        if (t < 7) {
            char* bh = smem + OFF_SX + ((t + 1) & 1) * 32768;
            char* bl = bh + 16384;
            const int j0n = (t + 1) * 128;
#pragma unroll
            for (int vb = 0; vb < 16; vb += 4) {
                float2 b2[4];
#pragma unroll
                for (int u = 0; u < 4; u++)
                    b2[u] = *(const float2*)(g_Bv + (j0n + warp * 16 + vb + u) * HD + 2 * lane);
#pragma unroll
                for (int u = 0; u < 4; u++) {
                    int jl = warp * 16 + vb + u;
                    float x0 = tanh_fast(ak0 + b2[u].x);
                    float x1v = tanh_fast(ak1 + b2[u].y);
                    uint32_t hw = bf16x2_pack(x0, x1v);
                    float h0f = __uint_as_float(hw << 16);
                    float h1f = __uint_as_float(hw & 0xFFFF0000u);
                    uint32_t lw = bf16x2_pack(x0 - h0f, x1v - h1f);
                    uint32_t sw = sw128((uint32_t)jl * 128 + lane * 4);
                    *(uint32_t*)(bh + sw) = hw;
                    *(uint32_t*)(bl + sw) = lw;
                }
            }
        }

        // MMA on buffer t&1 — fused per-ks loop, each fragment loaded once
        float acc[4][2][4];
#pragma unroll
        for (int mt = 0; mt < 4; mt++)
#pragma unroll
            for (int nt = 0; nt < 2; nt++)
#pragma unroll
                for (int c = 0; c < 4; c++) acc[mt][nt][c] = 0.0f;

        const uint32_t aHi = smem_base + OFF_SX + (t & 1) * 32768;
        const uint32_t aLo = aHi + 16384;
        const uint32_t bHi = smem_base + OFF_SW_HI;
        const uint32_t bLo = smem_base + OFF_SW_LO;
#pragma unroll
        for (int ks = 0; ks < 4; ks++) {
            const uint32_t kb = ks * 32;
            const uint32_t bOff = rowBoff + ((kb + kaddB) ^ swB);
            uint32_t bh0, bh1, bh2, bh3, bl0, bl1, bl2, bl3;
            LDM4(bh0, bh1, bh2, bh3, bHi + bOff);
            LDM4(bl0, bl1, bl2, bl3, bLo + bOff);
#pragma unroll
            for (int mt = 0; mt < 4; mt++) {
                const uint32_t aOff = rowAoff[mt] + ((kb + kaddA) ^ swA[mt]);
                uint32_t ah0, ah1, ah2, ah3, al0, al1, al2, al3;
                LDM4(ah0, ah1, ah2, ah3, aHi + aOff);
                LDM4(al0, al1, al2, al3, aLo + aOff);
                MMA_BF16(acc[mt][0], ah0, ah1, ah2, ah3, bh0, bh1);
                MMA_BF16(acc[mt][1], ah0, ah1, ah2, ah3, bh2, bh3);
                MMA_BF16(acc[mt][0], al0, al1, al2, al3, bh0, bh1);
                MMA_BF16(acc[mt][1], al0, al1, al2, al3, bh2, bh3);
                MMA_BF16(acc[mt][0], ah0, ah1, ah2, ah3, bl0, bl1);
                MMA_BF16(acc[mt][1], ah0, ah1, ah2, ah3, bl2, bl3);
            }
        }

        // epilogue: tanh, weight by s_j, fold into colacc
        const float* sTile = sS + t * 128;
#pragma unroll
        for (int mt = 0; mt < 4; mt++) {
            float s_a = sTile[jb + mt * 16 + (lane >> 2)];
            float s_b = sTile[jb + mt * 16 + 8 + (lane >> 2)];
#pragma unroll
            for (int nt = 0; nt < 2; nt++) {
#pragma unroll
                for (int c = 0; c < 4; c++) {
                    float x2 = tanh_fast(acc[mt][nt][c] + bi2v[nt * 2 + (c & 1)]);
                    colacc[nt * 2 + (c & 1)] += (c < 2 ? s_a : s_b) * x2;
                }
            }
        }
        __syncthreads();   // buf (t+1) ready; buf t free for produce(t+2)
    }

    // =================== final reductions ===================
#pragma unroll
    for (int q = 0; q < 4; q++) {
        float v = colacc[q];
        v += __shfl_xor_sync(0xffffffffu, v, 4);
        v += __shfl_xor_sync(0xffffffffu, v, 8);
        v += __shfl_xor_sync(0xffffffffu, v, 16);
        colacc[q] = v;
    }
    if (lane < 4) {
#pragma unroll
        for (int nt = 0; nt < 2; nt++)
#pragma unroll
            for (int cb = 0; cb < 2; cb++)
                sWRed[(warp & 1) * 64 + rb + nt * 8 + lane * 2 + cb] = colacc[nt * 2 + cb];
    }
    sQRed[warp * 32 + lane] = qacc;
    {
        float v = ssum;
#pragma unroll
        for (int o = 16; o > 0; o >>= 1)
            v += __shfl_xor_sync(0xffffffffu, v, o);
        if (lane == 0) sSRed[warp] = v;
    }
    __syncthreads();

    if (tid < LD) {
        float q = 0.0f;
#pragma unroll
        for (int w = 0; w < 8; w++) q += sQRed[w * 32 + tid];
        float sst = 0.0f;
#pragma unroll
        for (int w = 0; w < 8; w++) sst += sSRed[w];
        float kv = sst * bi3[tid];
#pragma unroll
        for (int r = 0; r < HD; r++)
            kv += (sWRed[r] + sWRed[64 + r]) * Wi3[tid * HD + r];
        float v = kv + q;
        out[i * (LD + 1) + tid] = SELF_SCALE * g_SELF[i * LD + tid] + INT_SCALE * v;
        float av = fabsf(v);
#pragma unroll
        for (int o = 16; o > 0; o >>= 1)
            av += __shfl_down_sync(0xffffffffu, av, o);
        if (tid == 0)
            out[i * (LD + 1) + LD] = 0.1f + 0.05f * av;
    }
}

// ---------------------------------------------------------------------------
extern "C" void kernel_launch(void* const* d_in, const int* in_sizes, int n_in,
                              void* d_out, int out_size)
{
    const float* state   = (const float*)d_in[0];
    const float* Ws1     = (const float*)d_in[1];
    const float* bs1     = (const float*)d_in[2];
    const float* Ws2     = (const float*)d_in[3];
    const float* bs2     = (const float*)d_in[4];
    const float* Ws3     = (const float*)d_in[5];
    const float* bs3     = (const float*)d_in[6];
    const float* Wi1     = (const float*)d_in[7];
    const float* bi1     = (const float*)d_in[8];
    const float* Wi2     = (const float*)d_in[9];
    const float* bi2     = (const float*)d_in[10];
    const float* Wi3     = (const float*)d_in[11];
    const float* bi3     = (const float*)d_in[12];
    const float* phase_w = (const float*)d_in[13];
    const float* Wc      = (const float*)d_in[14];
    const float* bc      = (const float*)d_in[15];
    const float* aggr    = (const float*)d_in[16];
    float* out = (float*)d_out;

    cudaFuncSetAttribute(phase1_kernel,
                         cudaFuncAttributeMaxDynamicSharedMemorySize, P1_SMEM);
    cudaFuncSetAttribute(phase2_kernel,
                         cudaFuncAttributeMaxDynamicSharedMemorySize, SMEM_TOT);

    phase1_kernel<<<128, NT, P1_SMEM>>>(state, Ws1, bs1, Ws2, bs2, Ws3, bs3,
                                        Wi1, bi1, Wc, aggr, phase_w);
    phase2_kernel<<<NB, NT, SMEM_TOT>>>(Wi2, bi2, Wi3, bi3, bc, out);
}